// round 1
// baseline (speedup 1.0000x reference)
#include <cuda_runtime.h>
#include <cuda_bf16.h>
#include <math.h>

#define BATCH 2
#define SEQ   2048
#define DMODEL 768
#define NHEADS 12
#define HDIM  64
#define MROWS (BATCH*SEQ)   // 4096

// ---------------- scratch (device globals; allocation-free) ----------------
__device__ float g_q[MROWS * DMODEL];
__device__ float g_k[MROWS * DMODEL];
__device__ float g_v[MROWS * DMODEL];
__device__ float g_att[MROWS * DMODEL];
__device__ float g_cos[SEQ * (HDIM/2)];
__device__ float g_sin[SEQ * (HDIM/2)];

// ---------------- RoPE table ----------------
__global__ void rope_table_kernel(float* ct, float* st) {
    int idx = blockIdx.x * blockDim.x + threadIdx.x;
    if (idx >= SEQ * (HDIM/2)) return;
    int t = idx >> 5;        // HDIM/2 = 32
    int i = idx & 31;
    float inv_freq = powf(10000.0f, -(float)(2 * i) / (float)HDIM);
    float ang = (float)t * inv_freq;
    ct[idx] = cosf(ang);
    st[idx] = sinf(ang);
}

// ---------------- RoPE apply (in place, q and k) ----------------
__global__ void rope_apply_kernel(float* q, float* k, const float* ct, const float* st) {
    int idx = blockIdx.x * blockDim.x + threadIdx.x; // over MROWS*NHEADS*32
    if (idx >= MROWS * NHEADS * 32) return;
    int i   = idx & 31;
    int h   = (idx >> 5) % NHEADS;
    int row = idx / (32 * NHEADS);    // b*SEQ + t
    int t   = row % SEQ;
    float c = ct[t * 32 + i];
    float s = st[t * 32 + i];
    size_t base = (size_t)row * DMODEL + h * HDIM;
    float x1 = q[base + i], x2 = q[base + 32 + i];
    q[base + i]      = x1 * c - x2 * s;
    q[base + 32 + i] = x1 * s + x2 * c;
    x1 = k[base + i]; x2 = k[base + 32 + i];
    k[base + i]      = x1 * c - x2 * s;
    k[base + 32 + i] = x1 * s + x2 * c;
}

// ---------------- SGEMM: C[M,N] = A[M,K] @ B[K,N], fp32 ----------------
// 128x128 block tile, K-step 8, 256 threads, 8x8 microtile per thread.
// Requires M%128==0, N%128==0, K%8==0, N%4==0 (true here: 4096,768,768).
__global__ __launch_bounds__(256, 2)
void sgemm128_kernel(const float* __restrict__ A, const float* __restrict__ B,
                     float* __restrict__ C, int M, int N, int K) {
    __shared__ float As[8][128];
    __shared__ float Bs[8][128];
    int tid = threadIdx.x;
    int tx = tid & 15;        // 0..15  (n direction)
    int ty = tid >> 4;        // 0..15  (m direction)
    int bm = blockIdx.y * 128;
    int bn = blockIdx.x * 128;

    int aRow = tid >> 1;             // 0..127
    int aCol = (tid & 1) * 4;        // 0 or 4
    int bRow = tid >> 5;             // 0..7
    int bCol = (tid & 31) * 4;       // 0..124

    const float* Aptr = A + (size_t)(bm + aRow) * K + aCol;
    const float* Bptr = B + (size_t)bRow * N + bn + bCol;

    float acc[8][8];
#pragma unroll
    for (int i = 0; i < 8; i++)
#pragma unroll
        for (int j = 0; j < 8; j++) acc[i][j] = 0.0f;

    for (int k0 = 0; k0 < K; k0 += 8) {
        float4 av = *(const float4*)(Aptr + k0);
        As[aCol + 0][aRow] = av.x;
        As[aCol + 1][aRow] = av.y;
        As[aCol + 2][aRow] = av.z;
        As[aCol + 3][aRow] = av.w;
        float4 bv = *(const float4*)(Bptr + (size_t)k0 * N);
        *(float4*)&Bs[bRow][bCol] = bv;
        __syncthreads();
#pragma unroll
        for (int kk = 0; kk < 8; kk++) {
            float a[8], b[8];
#pragma unroll
            for (int i = 0; i < 8; i++) a[i] = As[kk][ty * 8 + i];
#pragma unroll
            for (int j = 0; j < 8; j++) b[j] = Bs[kk][tx * 8 + j];
#pragma unroll
            for (int i = 0; i < 8; i++)
#pragma unroll
                for (int j = 0; j < 8; j++)
                    acc[i][j] = fmaf(a[i], b[j], acc[i][j]);
        }
        __syncthreads();
    }

#pragma unroll
    for (int i = 0; i < 8; i++) {
        float* Crow = C + (size_t)(bm + ty * 8 + i) * N + bn + tx * 8;
#pragma unroll
        for (int j = 0; j < 8; j += 4) {
            float4 o; o.x = acc[i][j]; o.y = acc[i][j+1]; o.z = acc[i][j+2]; o.w = acc[i][j+3];
            *(float4*)(Crow + j) = o;
        }
    }
}

// ---------------- causal flash attention ----------------
// grid: (SEQ/64, NHEADS, BATCH), block: 64 threads (1 query row per thread).
__global__ __launch_bounds__(64)
void attn_kernel(const float* __restrict__ q, const float* __restrict__ k,
                 const float* __restrict__ v, float* __restrict__ o) {
    int qt  = blockIdx.x;    // query tile 0..31
    int h   = blockIdx.y;
    int b   = blockIdx.z;
    int tid = threadIdx.x;   // 0..63
    int qrow = qt * 64 + tid;

    __shared__ float Ks[64][64];
    __shared__ float Vs[64][64];

    const float scale = 0.125f;  // 1/sqrt(64)
    float qv[64];
    {
        const float* qp = q + ((size_t)(b * SEQ + qrow)) * DMODEL + h * HDIM;
#pragma unroll
        for (int d = 0; d < 64; d++) qv[d] = qp[d] * scale;
    }
    float acc[64];
#pragma unroll
    for (int d = 0; d < 64; d++) acc[d] = 0.0f;
    float m = -1e30f, l = 0.0f;

    for (int kt = 0; kt <= qt; kt++) {
        // cooperative coalesced load of K,V tiles (thread tid loads column tid)
        const size_t kvbase = ((size_t)(b * SEQ + kt * 64)) * DMODEL + h * HDIM + tid;
#pragma unroll 4
        for (int r = 0; r < 64; r++) {
            Ks[r][tid] = k[kvbase + (size_t)r * DMODEL];
            Vs[r][tid] = v[kvbase + (size_t)r * DMODEL];
        }
        __syncthreads();

        for (int c0 = 0; c0 < 64; c0 += 16) {
            if (kt == qt && c0 > tid) break;   // fully-masked chunk
            float s[16];
            float cmax = -1e30f;
#pragma unroll
            for (int jj = 0; jj < 16; jj++) {
                int j = c0 + jj;
                float sum = 0.0f;
#pragma unroll
                for (int d = 0; d < 64; d++) sum = fmaf(qv[d], Ks[j][d], sum);
                bool valid = (kt * 64 + j) <= qrow;
                s[jj] = valid ? sum : -1e30f;
                cmax = fmaxf(cmax, s[jj]);
            }
            float newm = fmaxf(m, cmax);
            float corr = __expf(m - newm);
            l *= corr;
#pragma unroll
            for (int d = 0; d < 64; d++) acc[d] *= corr;
#pragma unroll
            for (int jj = 0; jj < 16; jj++) {
                float p = __expf(s[jj] - newm);
                l += p;
#pragma unroll
                for (int d = 0; d < 64; d++)
                    acc[d] = fmaf(p, Vs[c0 + jj][d], acc[d]);
            }
            m = newm;
        }
        __syncthreads();
    }

    float inv = 1.0f / l;
    float* op = o + ((size_t)(b * SEQ + qrow)) * DMODEL + h * HDIM;
#pragma unroll
    for (int d = 0; d < 64; d++) op[d] = acc[d] * inv;
}

// ---------------- launch ----------------
extern "C" void kernel_launch(void* const* d_in, const int* in_sizes, int n_in,
                              void* d_out, int out_size) {
    const float* x  = (const float*)d_in[0];
    const float* Wq = (const float*)d_in[1];
    const float* Wk = (const float*)d_in[2];
    const float* Wv = (const float*)d_in[3];
    const float* Wo = (const float*)d_in[4];
    float* out = (float*)d_out;

    float *q, *k, *v, *att, *ct, *st;
    cudaGetSymbolAddress((void**)&q,   g_q);
    cudaGetSymbolAddress((void**)&k,   g_k);
    cudaGetSymbolAddress((void**)&v,   g_v);
    cudaGetSymbolAddress((void**)&att, g_att);
    cudaGetSymbolAddress((void**)&ct,  g_cos);
    cudaGetSymbolAddress((void**)&st,  g_sin);

    // RoPE tables
    {
        int n = SEQ * (HDIM/2);
        rope_table_kernel<<<(n + 255) / 256, 256>>>(ct, st);
    }

    // QKV projections
    dim3 ggrid(DMODEL / 128, MROWS / 128);   // (6, 32)
    sgemm128_kernel<<<ggrid, 256>>>(x, Wq, q, MROWS, DMODEL, DMODEL);
    sgemm128_kernel<<<ggrid, 256>>>(x, Wk, k, MROWS, DMODEL, DMODEL);
    sgemm128_kernel<<<ggrid, 256>>>(x, Wv, v, MROWS, DMODEL, DMODEL);

    // RoPE on q,k
    {
        int n = MROWS * NHEADS * 32;
        rope_apply_kernel<<<(n + 255) / 256, 256>>>(q, k, ct, st);
    }

    // causal attention
    attn_kernel<<<dim3(SEQ / 64, NHEADS, BATCH), 64>>>(q, k, v, att);

    // output projection
    sgemm128_kernel<<<ggrid, 256>>>(att, Wo, out, MROWS, DMODEL, DMODEL);
}

// round 3
// speedup vs baseline: 1.9270x; 1.9270x over previous
#include <cuda_runtime.h>
#include <cuda_bf16.h>
#include <math.h>

#define BATCH 2
#define SEQ   2048
#define DMODEL 768
#define NHEADS 12
#define HDIM  64
#define MROWS (BATCH*SEQ)   // 4096

// ---------------- scratch (device globals; allocation-free) ----------------
__device__ float g_q[MROWS * DMODEL];
__device__ float g_k[MROWS * DMODEL];
__device__ float g_v[MROWS * DMODEL];
__device__ float g_att[MROWS * DMODEL];
__device__ float g_cos[SEQ * (HDIM/2)];
__device__ float g_sin[SEQ * (HDIM/2)];

// ---------------- tf32 helpers ----------------
__device__ __forceinline__ unsigned f2tf32(float x) {
    unsigned r;
    asm("cvt.rna.tf32.f32 %0, %1;\n" : "=r"(r) : "f"(x));
    return r;
}
__device__ __forceinline__ void split_tf32(float x, unsigned& hi, unsigned& lo) {
    hi = f2tf32(x);
    lo = f2tf32(x - __uint_as_float(hi));
}

__device__ __forceinline__ void mma_tf32(float* d, const unsigned* a, const unsigned* b, const float* c) {
    asm volatile(
        "mma.sync.aligned.m16n8k8.row.col.f32.tf32.tf32.f32 "
        "{%0,%1,%2,%3}, {%4,%5,%6,%7}, {%8,%9}, {%10,%11,%12,%13};\n"
        : "=f"(d[0]), "=f"(d[1]), "=f"(d[2]), "=f"(d[3])
        : "r"(a[0]), "r"(a[1]), "r"(a[2]), "r"(a[3]),
          "r"(b[0]), "r"(b[1]),
          "f"(c[0]), "f"(c[1]), "f"(c[2]), "f"(c[3]));
}
// 3xTF32: d += Ahi*Bhi + Ahi*Blo + Alo*Bhi
__device__ __forceinline__ void mma3(float* d, const unsigned* ah, const unsigned* al,
                                     const unsigned* bh, const unsigned* bl) {
    mma_tf32(d, al, bh, d);
    mma_tf32(d, ah, bl, d);
    mma_tf32(d, ah, bh, d);
}

__device__ __forceinline__ void cp_async16(void* smem, const void* gmem) {
    unsigned s = (unsigned)__cvta_generic_to_shared(smem);
    asm volatile("cp.async.cg.shared.global [%0], [%1], 16;\n" :: "r"(s), "l"(gmem));
}
__device__ __forceinline__ void cp_commit() { asm volatile("cp.async.commit_group;\n"); }
template<int N> __device__ __forceinline__ void cp_wait() {
    asm volatile("cp.async.wait_group %0;\n" :: "n"(N));
}

// ---------------- RoPE table ----------------
__global__ void rope_table_kernel(float* ct, float* st) {
    int idx = blockIdx.x * blockDim.x + threadIdx.x;
    if (idx >= SEQ * (HDIM/2)) return;
    int t = idx >> 5;
    int i = idx & 31;
    float inv_freq = powf(10000.0f, -(float)(2 * i) / (float)HDIM);
    float ang = (float)t * inv_freq;
    ct[idx] = cosf(ang);
    st[idx] = sinf(ang);
}

// ---------------- RoPE apply (in place, q and k) ----------------
__global__ void rope_apply_kernel(float* q, float* k, const float* ct, const float* st) {
    int idx = blockIdx.x * blockDim.x + threadIdx.x;
    if (idx >= MROWS * NHEADS * 32) return;
    int i   = idx & 31;
    int h   = (idx >> 5) % NHEADS;
    int row = idx / (32 * NHEADS);
    int t   = row % SEQ;
    float c = ct[t * 32 + i];
    float s = st[t * 32 + i];
    size_t base = (size_t)row * DMODEL + h * HDIM;
    float x1 = q[base + i], x2 = q[base + 32 + i];
    q[base + i]      = x1 * c - x2 * s;
    q[base + 32 + i] = x1 * s + x2 * c;
    x1 = k[base + i]; x2 = k[base + 32 + i];
    k[base + i]      = x1 * c - x2 * s;
    k[base + 32 + i] = x1 * s + x2 * c;
}

// ---------------- 3xtf32 tensor-core GEMM: C[4096,768] = A[4096,768] @ B[768,768] ----------------
__global__ __launch_bounds__(256)
void gemm_tf32_kernel(const float* __restrict__ A, const float* __restrict__ B,
                      float* __restrict__ C) {
    const int K = DMODEL, N = DMODEL;
    __shared__ __align__(16) float As[2][128][20];   // [m][k], stride 20
    __shared__ __align__(16) float Bs[2][16][136];   // [k][n], stride 136

    int tid  = threadIdx.x;
    int wid  = tid >> 5, lane = tid & 31;
    int g = lane >> 2, c = lane & 3;
    int wm = (wid & 3) * 32;
    int wn = (wid >> 2) * 64;
    int bm = blockIdx.y * 128, bn = blockIdx.x * 128;

    int arow0 = tid >> 2,  acol = (tid & 3) * 4;
    int brow0 = tid >> 5,  bcol = (tid & 31) * 4;

    float acc[2][8][4];
#pragma unroll
    for (int mf = 0; mf < 2; mf++)
#pragma unroll
        for (int nf = 0; nf < 8; nf++)
#pragma unroll
            for (int j = 0; j < 4; j++) acc[mf][nf][j] = 0.0f;

    auto load_chunk = [&](int buf, int k0) {
        cp_async16(&As[buf][arow0][acol],      A + (size_t)(bm + arow0) * K + k0 + acol);
        cp_async16(&As[buf][arow0 + 64][acol], A + (size_t)(bm + arow0 + 64) * K + k0 + acol);
        cp_async16(&Bs[buf][brow0][bcol],      B + (size_t)(k0 + brow0) * N + bn + bcol);
        cp_async16(&Bs[buf][brow0 + 8][bcol],  B + (size_t)(k0 + brow0 + 8) * N + bn + bcol);
    };

    const int NCH = K / 16;  // 48
    load_chunk(0, 0); cp_commit();

    for (int ch = 0; ch < NCH; ch++) {
        int buf = ch & 1;
        if (ch + 1 < NCH) { load_chunk(buf ^ 1, (ch + 1) * 16); cp_commit(); cp_wait<1>(); }
        else              { cp_wait<0>(); }
        __syncthreads();

#pragma unroll
        for (int ks = 0; ks < 2; ks++) {
            int k0 = ks * 8;
            unsigned afh[2][4], afl[2][4], bfh[8][2], bfl[8][2];
#pragma unroll
            for (int mf = 0; mf < 2; mf++) {
                int m0 = wm + mf * 16;
                split_tf32(As[buf][m0 + g    ][k0 + c    ], afh[mf][0], afl[mf][0]);
                split_tf32(As[buf][m0 + g + 8][k0 + c    ], afh[mf][1], afl[mf][1]);
                split_tf32(As[buf][m0 + g    ][k0 + c + 4], afh[mf][2], afl[mf][2]);
                split_tf32(As[buf][m0 + g + 8][k0 + c + 4], afh[mf][3], afl[mf][3]);
            }
#pragma unroll
            for (int nf = 0; nf < 8; nf++) {
                split_tf32(Bs[buf][k0 + c    ][wn + nf * 8 + g], bfh[nf][0], bfl[nf][0]);
                split_tf32(Bs[buf][k0 + c + 4][wn + nf * 8 + g], bfh[nf][1], bfl[nf][1]);
            }
#pragma unroll
            for (int mf = 0; mf < 2; mf++)
#pragma unroll
                for (int nf = 0; nf < 8; nf++)
                    mma3(acc[mf][nf], afh[mf], afl[mf], bfh[nf], bfl[nf]);
        }
        __syncthreads();
    }

#pragma unroll
    for (int mf = 0; mf < 2; mf++) {
        int row0 = bm + wm + mf * 16 + g;
#pragma unroll
        for (int nf = 0; nf < 8; nf++) {
            int col = bn + wn + nf * 8 + 2 * c;
            float2 v0 = make_float2(acc[mf][nf][0], acc[mf][nf][1]);
            float2 v1 = make_float2(acc[mf][nf][2], acc[mf][nf][3]);
            *(float2*)(C + (size_t)row0 * N + col)       = v0;
            *(float2*)(C + (size_t)(row0 + 8) * N + col) = v1;
        }
    }
}

// ---------------- 3xtf32 tensor-core causal flash attention ----------------
// grid: (SEQ/64, NHEADS, BATCH), 128 threads (4 warps), 16 q-rows per warp.
__global__ __launch_bounds__(128)
void attn_tf32_kernel(const float* __restrict__ q, const float* __restrict__ k,
                      const float* __restrict__ v, float* __restrict__ o) {
    __shared__ __align__(16) float Ks[64][72];
    __shared__ __align__(16) float Vs[64][72];

    int qt = blockIdx.x, h = blockIdx.y, b = blockIdx.z;
    int tid = threadIdx.x;
    int warp = tid >> 5, lane = tid & 31;
    int g = lane >> 2, c = lane & 3;

    // Q fragments (A operand), scale folded in, pre-split hi/lo
    unsigned qah[8][4], qal[8][4];
    {
        const float* qp = q + (size_t)(b * SEQ + qt * 64 + warp * 16) * DMODEL + h * HDIM;
#pragma unroll
        for (int ks = 0; ks < 8; ks++) {
            split_tf32(qp[(size_t)g * DMODEL       + ks * 8 + c    ] * 0.125f, qah[ks][0], qal[ks][0]);
            split_tf32(qp[(size_t)(g + 8) * DMODEL + ks * 8 + c    ] * 0.125f, qah[ks][1], qal[ks][1]);
            split_tf32(qp[(size_t)g * DMODEL       + ks * 8 + c + 4] * 0.125f, qah[ks][2], qal[ks][2]);
            split_tf32(qp[(size_t)(g + 8) * DMODEL + ks * 8 + c + 4] * 0.125f, qah[ks][3], qal[ks][3]);
        }
    }

    float oacc[8][4];
#pragma unroll
    for (int nf = 0; nf < 8; nf++)
#pragma unroll
        for (int j = 0; j < 4; j++) oacc[nf][j] = 0.0f;
    float m0 = -1e30f, m1 = -1e30f, l0 = 0.0f, l1 = 0.0f;
    int qr0 = qt * 64 + warp * 16 + g;
    int qr1 = qr0 + 8;

    for (int kt = 0; kt <= qt; kt++) {
        const float* kb_ = k + (size_t)(b * SEQ + kt * 64) * DMODEL + h * HDIM;
        const float* vb_ = v + (size_t)(b * SEQ + kt * 64) * DMODEL + h * HDIM;
#pragma unroll 2
        for (int i = tid; i < 64 * 16; i += 128) {
            int row = i >> 4, c4 = (i & 15) * 4;
            *(float4*)&Ks[row][c4] = *(const float4*)&kb_[(size_t)row * DMODEL + c4];
            *(float4*)&Vs[row][c4] = *(const float4*)&vb_[(size_t)row * DMODEL + c4];
        }
        __syncthreads();

        int nblk = (kt == qt) ? (2 * warp + 2) : 8;

        // S = Q K^T  (3xtf32)
        float sc[8][4];
        for (int nf = 0; nf < nblk; nf++) {
#pragma unroll
            for (int j = 0; j < 4; j++) sc[nf][j] = 0.0f;
#pragma unroll
            for (int ks = 0; ks < 8; ks++) {
                unsigned bh[2], bl[2];
                split_tf32(Ks[nf * 8 + g][ks * 8 + c    ], bh[0], bl[0]);
                split_tf32(Ks[nf * 8 + g][ks * 8 + c + 4], bh[1], bl[1]);
                mma3(sc[nf], qah[ks], qal[ks], bh, bl);
            }
        }

        // causal mask (diagonal tile only)
        if (kt == qt) {
            for (int nf = 0; nf < nblk; nf++) {
#pragma unroll
                for (int j = 0; j < 4; j++) {
                    int key = kt * 64 + nf * 8 + 2 * c + (j & 1);
                    int qr  = (j < 2) ? qr0 : qr1;
                    if (key > qr) sc[nf][j] = -1e30f;
                }
            }
        }

        // online softmax
        float mx0 = -1e30f, mx1 = -1e30f;
        for (int nf = 0; nf < nblk; nf++) {
            mx0 = fmaxf(mx0, fmaxf(sc[nf][0], sc[nf][1]));
            mx1 = fmaxf(mx1, fmaxf(sc[nf][2], sc[nf][3]));
        }
        mx0 = fmaxf(mx0, __shfl_xor_sync(0xffffffffu, mx0, 1));
        mx0 = fmaxf(mx0, __shfl_xor_sync(0xffffffffu, mx0, 2));
        mx1 = fmaxf(mx1, __shfl_xor_sync(0xffffffffu, mx1, 1));
        mx1 = fmaxf(mx1, __shfl_xor_sync(0xffffffffu, mx1, 2));
        float nm0 = fmaxf(m0, mx0), nm1 = fmaxf(m1, mx1);
        float cor0 = __expf(m0 - nm0), cor1 = __expf(m1 - nm1);
        m0 = nm0; m1 = nm1;
        l0 *= cor0; l1 *= cor1;
#pragma unroll
        for (int nf = 0; nf < 8; nf++) {
            oacc[nf][0] *= cor0; oacc[nf][1] *= cor0;
            oacc[nf][2] *= cor1; oacc[nf][3] *= cor1;
        }
        for (int nf = 0; nf < nblk; nf++) {
            sc[nf][0] = __expf(sc[nf][0] - m0);
            sc[nf][1] = __expf(sc[nf][1] - m0);
            sc[nf][2] = __expf(sc[nf][2] - m1);
            sc[nf][3] = __expf(sc[nf][3] - m1);
            l0 += sc[nf][0] + sc[nf][1];
            l1 += sc[nf][2] + sc[nf][3];
        }

        // O += P V  (C-layout -> A-layout via quad shuffles, 3xtf32)
        for (int kb = 0; kb < nblk; kb++) {
            float p0 = sc[kb][0], p1 = sc[kb][1], p2 = sc[kb][2], p3 = sc[kb][3];
            int src0 = (lane & ~3) + (c >> 1);
            int src1 = src0 + 2;
            float t0 = __shfl_sync(0xffffffffu, p0, src0);
            float t1 = __shfl_sync(0xffffffffu, p1, src0);
            float t2 = __shfl_sync(0xffffffffu, p2, src0);
            float t3 = __shfl_sync(0xffffffffu, p3, src0);
            float u0 = __shfl_sync(0xffffffffu, p0, src1);
            float u1 = __shfl_sync(0xffffffffu, p1, src1);
            float u2 = __shfl_sync(0xffffffffu, p2, src1);
            float u3 = __shfl_sync(0xffffffffu, p3, src1);
            unsigned ah[4], al[4];
            split_tf32((c & 1) ? t1 : t0, ah[0], al[0]);
            split_tf32((c & 1) ? t3 : t2, ah[1], al[1]);
            split_tf32((c & 1) ? u1 : u0, ah[2], al[2]);
            split_tf32((c & 1) ? u3 : u2, ah[3], al[3]);
#pragma unroll
            for (int nf2 = 0; nf2 < 8; nf2++) {
                unsigned bh[2], bl[2];
                split_tf32(Vs[kb * 8 + c    ][nf2 * 8 + g], bh[0], bl[0]);
                split_tf32(Vs[kb * 8 + c + 4][nf2 * 8 + g], bh[1], bl[1]);
                mma3(oacc[nf2], ah, al, bh, bl);
            }
        }
        __syncthreads();
    }

    // finalize: quad-sum l, normalize, write
    l0 += __shfl_xor_sync(0xffffffffu, l0, 1);
    l0 += __shfl_xor_sync(0xffffffffu, l0, 2);
    l1 += __shfl_xor_sync(0xffffffffu, l1, 1);
    l1 += __shfl_xor_sync(0xffffffffu, l1, 2);
    float inv0 = 1.0f / l0, inv1 = 1.0f / l1;

    float* op0 = o + (size_t)(b * SEQ + qr0) * DMODEL + h * HDIM;
    float* op1 = o + (size_t)(b * SEQ + qr1) * DMODEL + h * HDIM;
#pragma unroll
    for (int nf = 0; nf < 8; nf++) {
        int col = nf * 8 + 2 * c;
        *(float2*)(op0 + col) = make_float2(oacc[nf][0] * inv0, oacc[nf][1] * inv0);
        *(float2*)(op1 + col) = make_float2(oacc[nf][2] * inv1, oacc[nf][3] * inv1);
    }
}

// ---------------- launch ----------------
extern "C" void kernel_launch(void* const* d_in, const int* in_sizes, int n_in,
                              void* d_out, int out_size) {
    const float* x  = (const float*)d_in[0];
    const float* Wq = (const float*)d_in[1];
    const float* Wk = (const float*)d_in[2];
    const float* Wv = (const float*)d_in[3];
    const float* Wo = (const float*)d_in[4];
    float* out = (float*)d_out;

    float *q, *k, *v, *att, *ct, *st;
    cudaGetSymbolAddress((void**)&q,   g_q);
    cudaGetSymbolAddress((void**)&k,   g_k);
    cudaGetSymbolAddress((void**)&v,   g_v);
    cudaGetSymbolAddress((void**)&att, g_att);
    cudaGetSymbolAddress((void**)&ct,  g_cos);
    cudaGetSymbolAddress((void**)&st,  g_sin);

    {
        int n = SEQ * (HDIM/2);
        rope_table_kernel<<<(n + 255) / 256, 256>>>(ct, st);
    }

    dim3 ggrid(DMODEL / 128, MROWS / 128);   // (6, 32)
    gemm_tf32_kernel<<<ggrid, 256>>>(x, Wq, q);
    gemm_tf32_kernel<<<ggrid, 256>>>(x, Wk, k);
    gemm_tf32_kernel<<<ggrid, 256>>>(x, Wv, v);

    {
        int n = MROWS * NHEADS * 32;
        rope_apply_kernel<<<(n + 255) / 256, 256>>>(q, k, ct, st);
    }

    attn_tf32_kernel<<<dim3(SEQ / 64, NHEADS, BATCH), 128>>>(q, k, v, att);

    gemm_tf32_kernel<<<ggrid, 256>>>(att, Wo, out);
}

// round 4
// speedup vs baseline: 2.2013x; 1.1423x over previous
#include <cuda_runtime.h>
#include <cuda_bf16.h>
#include <math.h>

#define BATCH 2
#define SEQ   2048
#define DMODEL 768
#define NHEADS 12
#define HDIM  64
#define MROWS (BATCH*SEQ)   // 4096
#define NELEM (MROWS*DMODEL)
#define WELEM (DMODEL*DMODEL)

// ---------------- scratch (device globals; allocation-free) ----------------
__device__ float g_xh[NELEM], g_xl[NELEM];
__device__ float g_wh[4][WELEM], g_wl[4][WELEM];
__device__ float g_qraw[NELEM], g_kraw[NELEM];
__device__ float g_qh[NELEM], g_ql[NELEM];
__device__ float g_kh[NELEM], g_kl[NELEM];
__device__ float g_vh[NELEM], g_vl[NELEM];
__device__ float g_ath[NELEM], g_atl[NELEM];
__device__ float g_cos[SEQ * (HDIM/2)];
__device__ float g_sin[SEQ * (HDIM/2)];

// ---------------- tf32 helpers ----------------
__device__ __forceinline__ unsigned f2tf32(float x) {
    unsigned r;
    asm("cvt.rna.tf32.f32 %0, %1;\n" : "=r"(r) : "f"(x));
    return r;
}
__device__ __forceinline__ void split_tf32(float x, unsigned& hi, unsigned& lo) {
    hi = f2tf32(x);
    lo = f2tf32(x - __uint_as_float(hi));
}
__device__ __forceinline__ void split_store(float x, float* hp, float* lp) {
    unsigned h, l; split_tf32(x, h, l);
    *hp = __uint_as_float(h);
    *lp = __uint_as_float(l);
}

__device__ __forceinline__ void mma_tf32(float* d, const unsigned* a, const unsigned* b, const float* c) {
    asm volatile(
        "mma.sync.aligned.m16n8k8.row.col.f32.tf32.tf32.f32 "
        "{%0,%1,%2,%3}, {%4,%5,%6,%7}, {%8,%9}, {%10,%11,%12,%13};\n"
        : "=f"(d[0]), "=f"(d[1]), "=f"(d[2]), "=f"(d[3])
        : "r"(a[0]), "r"(a[1]), "r"(a[2]), "r"(a[3]),
          "r"(b[0]), "r"(b[1]),
          "f"(c[0]), "f"(c[1]), "f"(c[2]), "f"(c[3]));
}
__device__ __forceinline__ void mma3(float* d, const unsigned* ah, const unsigned* al,
                                     const unsigned* bh, const unsigned* bl) {
    mma_tf32(d, al, bh, d);
    mma_tf32(d, ah, bl, d);
    mma_tf32(d, ah, bh, d);
}

__device__ __forceinline__ void cp_async16(void* smem, const void* gmem) {
    unsigned s = (unsigned)__cvta_generic_to_shared(smem);
    asm volatile("cp.async.cg.shared.global [%0], [%1], 16;\n" :: "r"(s), "l"(gmem));
}
__device__ __forceinline__ void cp_commit() { asm volatile("cp.async.commit_group;\n"); }
template<int N> __device__ __forceinline__ void cp_wait() {
    asm volatile("cp.async.wait_group %0;\n" :: "n"(N));
}

// ---------------- prepass: generic fp32 -> (tf32 hi, tf32 lo) ----------------
__global__ void split_kernel(const float* __restrict__ src, float* __restrict__ hi,
                             float* __restrict__ lo, int n) {
    int i = blockIdx.x * blockDim.x + threadIdx.x;
    if (i >= n) return;
    split_store(src[i], hi + i, lo + i);
}

// ---------------- RoPE table ----------------
__global__ void rope_table_kernel(float* ct, float* st) {
    int idx = blockIdx.x * blockDim.x + threadIdx.x;
    if (idx >= SEQ * (HDIM/2)) return;
    int t = idx >> 5;
    int i = idx & 31;
    float inv_freq = powf(10000.0f, -(float)(2 * i) / (float)HDIM);
    float ang = (float)t * inv_freq;
    ct[idx] = cosf(ang);
    st[idx] = sinf(ang);
}

// ---------------- fused RoPE + split (q gets 0.125 scale folded) ----------------
__global__ void rope_split_kernel(const float* __restrict__ q, const float* __restrict__ k,
                                  const float* __restrict__ ct, const float* __restrict__ st,
                                  float* qh, float* ql, float* kh, float* kl) {
    int idx = blockIdx.x * blockDim.x + threadIdx.x;
    if (idx >= MROWS * NHEADS * 32) return;
    int i   = idx & 31;
    int h   = (idx >> 5) % NHEADS;
    int row = idx / (32 * NHEADS);
    int t   = row % SEQ;
    float c = ct[t * 32 + i];
    float s = st[t * 32 + i];
    size_t base = (size_t)row * DMODEL + h * HDIM;
    float x1 = q[base + i], x2 = q[base + 32 + i];
    split_store((x1 * c - x2 * s) * 0.125f, qh + base + i,      ql + base + i);
    split_store((x1 * s + x2 * c) * 0.125f, qh + base + 32 + i, ql + base + 32 + i);
    x1 = k[base + i]; x2 = k[base + 32 + i];
    split_store(x1 * c - x2 * s, kh + base + i,      kl + base + i);
    split_store(x1 * s + x2 * c, kh + base + 32 + i, kl + base + 32 + i);
}

// ---------------- 3xtf32 GEMM on pre-split operands ----------------
// C[4096,768] = A[4096,768] @ B[768,768]. 128x128 tile, K-chunk 8, 256 threads.
// gridDim.z selects (B, C): z=0 -> C0 fp32, z=1 -> C1 fp32, z=2 -> split (C2h,C2l).
__global__ __launch_bounds__(256)
void gemm3_kernel(const float* __restrict__ Ah, const float* __restrict__ Al,
                  const float* __restrict__ Bh0, const float* __restrict__ Bl0,
                  const float* __restrict__ Bh1, const float* __restrict__ Bl1,
                  const float* __restrict__ Bh2, const float* __restrict__ Bl2,
                  float* __restrict__ C0, float* __restrict__ C1,
                  float* __restrict__ C2h, float* __restrict__ C2l) {
    const int K = DMODEL, N = DMODEL;
    __shared__ __align__(16) float Ah_s[2][128][12];
    __shared__ __align__(16) float Al_s[2][128][12];
    __shared__ __align__(16) float Bh_s[2][8][136];
    __shared__ __align__(16) float Bl_s[2][8][136];

    int z = blockIdx.z;
    const float* Bh = (z == 0) ? Bh0 : (z == 1) ? Bh1 : Bh2;
    const float* Bl = (z == 0) ? Bl0 : (z == 1) ? Bl1 : Bl2;

    int tid  = threadIdx.x;
    int wid  = tid >> 5, lane = tid & 31;
    int g = lane >> 2, c = lane & 3;
    int wm = (wid & 3) * 32;
    int wn = (wid >> 2) * 64;
    int bm = blockIdx.y * 128, bn = blockIdx.x * 128;

    int arow = tid >> 1,  acol = (tid & 1) * 4;
    int brow = tid >> 5,  bcol = (tid & 31) * 4;

    float acc[2][8][4];
#pragma unroll
    for (int mf = 0; mf < 2; mf++)
#pragma unroll
        for (int nf = 0; nf < 8; nf++)
#pragma unroll
            for (int j = 0; j < 4; j++) acc[mf][nf][j] = 0.0f;

    auto load_chunk = [&](int buf, int k0) {
        size_t aoff = (size_t)(bm + arow) * K + k0 + acol;
        cp_async16(&Ah_s[buf][arow][acol], Ah + aoff);
        cp_async16(&Al_s[buf][arow][acol], Al + aoff);
        size_t boff = (size_t)(k0 + brow) * N + bn + bcol;
        cp_async16(&Bh_s[buf][brow][bcol], Bh + boff);
        cp_async16(&Bl_s[buf][brow][bcol], Bl + boff);
    };

    const int NCH = K / 8;  // 96
    load_chunk(0, 0); cp_commit();

    for (int ch = 0; ch < NCH; ch++) {
        int buf = ch & 1;
        if (ch + 1 < NCH) { load_chunk(buf ^ 1, (ch + 1) * 8); cp_commit(); cp_wait<1>(); }
        else              { cp_wait<0>(); }
        __syncthreads();

        unsigned afh[2][4], afl[2][4], bfh[8][2], bfl[8][2];
#pragma unroll
        for (int mf = 0; mf < 2; mf++) {
            int m0 = wm + mf * 16;
            afh[mf][0] = __float_as_uint(Ah_s[buf][m0 + g    ][c    ]);
            afh[mf][1] = __float_as_uint(Ah_s[buf][m0 + g + 8][c    ]);
            afh[mf][2] = __float_as_uint(Ah_s[buf][m0 + g    ][c + 4]);
            afh[mf][3] = __float_as_uint(Ah_s[buf][m0 + g + 8][c + 4]);
            afl[mf][0] = __float_as_uint(Al_s[buf][m0 + g    ][c    ]);
            afl[mf][1] = __float_as_uint(Al_s[buf][m0 + g + 8][c    ]);
            afl[mf][2] = __float_as_uint(Al_s[buf][m0 + g    ][c + 4]);
            afl[mf][3] = __float_as_uint(Al_s[buf][m0 + g + 8][c + 4]);
        }
#pragma unroll
        for (int nf = 0; nf < 8; nf++) {
            int n0 = wn + nf * 8 + g;
            bfh[nf][0] = __float_as_uint(Bh_s[buf][c    ][n0]);
            bfh[nf][1] = __float_as_uint(Bh_s[buf][c + 4][n0]);
            bfl[nf][0] = __float_as_uint(Bl_s[buf][c    ][n0]);
            bfl[nf][1] = __float_as_uint(Bl_s[buf][c + 4][n0]);
        }
#pragma unroll
        for (int mf = 0; mf < 2; mf++)
#pragma unroll
            for (int nf = 0; nf < 8; nf++)
                mma3(acc[mf][nf], afh[mf], afl[mf], bfh[nf], bfl[nf]);
        __syncthreads();
    }

#pragma unroll
    for (int mf = 0; mf < 2; mf++) {
        int row0 = bm + wm + mf * 16 + g;
#pragma unroll
        for (int nf = 0; nf < 8; nf++) {
            int col = bn + wn + nf * 8 + 2 * c;
            size_t o0 = (size_t)row0 * N + col;
            size_t o1 = (size_t)(row0 + 8) * N + col;
            if (z == 2) {
                unsigned h, l;
                float2 h0, l0, h1, l1;
                split_tf32(acc[mf][nf][0], h, l); h0.x = __uint_as_float(h); l0.x = __uint_as_float(l);
                split_tf32(acc[mf][nf][1], h, l); h0.y = __uint_as_float(h); l0.y = __uint_as_float(l);
                split_tf32(acc[mf][nf][2], h, l); h1.x = __uint_as_float(h); l1.x = __uint_as_float(l);
                split_tf32(acc[mf][nf][3], h, l); h1.y = __uint_as_float(h); l1.y = __uint_as_float(l);
                *(float2*)(C2h + o0) = h0; *(float2*)(C2l + o0) = l0;
                *(float2*)(C2h + o1) = h1; *(float2*)(C2l + o1) = l1;
            } else {
                float* C = (z == 0) ? C0 : C1;
                *(float2*)(C + o0) = make_float2(acc[mf][nf][0], acc[mf][nf][1]);
                *(float2*)(C + o1) = make_float2(acc[mf][nf][2], acc[mf][nf][3]);
            }
        }
    }
}

// ---------------- 3xtf32 causal flash attention on pre-split q/k/v ----------------
// grid: (SEQ/64, NHEADS, BATCH), 128 threads (4 warps), 16 q-rows per warp.
// K and V tiles share one smem hi/lo buffer pair (phased).
__global__ __launch_bounds__(128)
void attn3_kernel(const float* __restrict__ qh, const float* __restrict__ ql,
                  const float* __restrict__ kh, const float* __restrict__ kl,
                  const float* __restrict__ vh, const float* __restrict__ vl,
                  float* __restrict__ oh, float* __restrict__ ol) {
    __shared__ __align__(16) float Sh[64][72];
    __shared__ __align__(16) float Sl[64][72];

    int qt = blockIdx.x, h = blockIdx.y, b = blockIdx.z;
    int tid = threadIdx.x;
    int warp = tid >> 5, lane = tid & 31;
    int g = lane >> 2, c = lane & 3;

    // Q fragments (A operand) from pre-split, pre-scaled arrays
    unsigned qah[8][4], qal[8][4];
    {
        size_t qb = (size_t)(b * SEQ + qt * 64 + warp * 16) * DMODEL + h * HDIM;
#pragma unroll
        for (int ks = 0; ks < 8; ks++) {
            size_t i00 = qb + (size_t)g * DMODEL       + ks * 8 + c;
            size_t i10 = qb + (size_t)(g + 8) * DMODEL + ks * 8 + c;
            qah[ks][0] = __float_as_uint(qh[i00]);
            qah[ks][1] = __float_as_uint(qh[i10]);
            qah[ks][2] = __float_as_uint(qh[i00 + 4]);
            qah[ks][3] = __float_as_uint(qh[i10 + 4]);
            qal[ks][0] = __float_as_uint(ql[i00]);
            qal[ks][1] = __float_as_uint(ql[i10]);
            qal[ks][2] = __float_as_uint(ql[i00 + 4]);
            qal[ks][3] = __float_as_uint(ql[i10 + 4]);
        }
    }

    float oacc[8][4];
#pragma unroll
    for (int nf = 0; nf < 8; nf++)
#pragma unroll
        for (int j = 0; j < 4; j++) oacc[nf][j] = 0.0f;
    float m0 = -1e30f, m1 = -1e30f, l0 = 0.0f, l1 = 0.0f;
    int qr0 = qt * 64 + warp * 16 + g;
    int qr1 = qr0 + 8;

    for (int kt = 0; kt <= qt; kt++) {
        size_t tb = (size_t)(b * SEQ + kt * 64) * DMODEL + h * HDIM;

        // phase A: K tile (hi/lo)
#pragma unroll
        for (int i = tid; i < 64 * 16; i += 128) {
            int row = i >> 4, c4 = (i & 15) * 4;
            size_t off = tb + (size_t)row * DMODEL + c4;
            cp_async16(&Sh[row][c4], kh + off);
            cp_async16(&Sl[row][c4], kl + off);
        }
        cp_commit(); cp_wait<0>();
        __syncthreads();

        int nblk = (kt == qt) ? (2 * warp + 2) : 8;

        // S = Q K^T (pure MMA)
        float sc[8][4];
        for (int nf = 0; nf < nblk; nf++) {
#pragma unroll
            for (int j = 0; j < 4; j++) sc[nf][j] = 0.0f;
#pragma unroll
            for (int ks = 0; ks < 8; ks++) {
                unsigned bh[2], bl[2];
                bh[0] = __float_as_uint(Sh[nf * 8 + g][ks * 8 + c    ]);
                bh[1] = __float_as_uint(Sh[nf * 8 + g][ks * 8 + c + 4]);
                bl[0] = __float_as_uint(Sl[nf * 8 + g][ks * 8 + c    ]);
                bl[1] = __float_as_uint(Sl[nf * 8 + g][ks * 8 + c + 4]);
                mma3(sc[nf], qah[ks], qal[ks], bh, bl);
            }
        }
        __syncthreads();   // all warps done reading K

        // phase B: V tile load (async, overlaps softmax math)
#pragma unroll
        for (int i = tid; i < 64 * 16; i += 128) {
            int row = i >> 4, c4 = (i & 15) * 4;
            size_t off = tb + (size_t)row * DMODEL + c4;
            cp_async16(&Sh[row][c4], vh + off);
            cp_async16(&Sl[row][c4], vl + off);
        }
        cp_commit();

        // causal mask (diagonal tile only)
        if (kt == qt) {
            for (int nf = 0; nf < nblk; nf++) {
#pragma unroll
                for (int j = 0; j < 4; j++) {
                    int key = kt * 64 + nf * 8 + 2 * c + (j & 1);
                    int qr  = (j < 2) ? qr0 : qr1;
                    if (key > qr) sc[nf][j] = -1e30f;
                }
            }
        }

        // online softmax
        float mx0 = -1e30f, mx1 = -1e30f;
        for (int nf = 0; nf < nblk; nf++) {
            mx0 = fmaxf(mx0, fmaxf(sc[nf][0], sc[nf][1]));
            mx1 = fmaxf(mx1, fmaxf(sc[nf][2], sc[nf][3]));
        }
        mx0 = fmaxf(mx0, __shfl_xor_sync(0xffffffffu, mx0, 1));
        mx0 = fmaxf(mx0, __shfl_xor_sync(0xffffffffu, mx0, 2));
        mx1 = fmaxf(mx1, __shfl_xor_sync(0xffffffffu, mx1, 1));
        mx1 = fmaxf(mx1, __shfl_xor_sync(0xffffffffu, mx1, 2));
        float nm0 = fmaxf(m0, mx0), nm1 = fmaxf(m1, mx1);
        float cor0 = __expf(m0 - nm0), cor1 = __expf(m1 - nm1);
        m0 = nm0; m1 = nm1;
        l0 *= cor0; l1 *= cor1;
#pragma unroll
        for (int nf = 0; nf < 8; nf++) {
            oacc[nf][0] *= cor0; oacc[nf][1] *= cor0;
            oacc[nf][2] *= cor1; oacc[nf][3] *= cor1;
        }
        for (int nf = 0; nf < nblk; nf++) {
            sc[nf][0] = __expf(sc[nf][0] - m0);
            sc[nf][1] = __expf(sc[nf][1] - m0);
            sc[nf][2] = __expf(sc[nf][2] - m1);
            sc[nf][3] = __expf(sc[nf][3] - m1);
            l0 += sc[nf][0] + sc[nf][1];
            l1 += sc[nf][2] + sc[nf][3];
        }

        cp_wait<0>();
        __syncthreads();   // V tile ready

        // O += P V  (P split in registers; V pre-split in smem)
        for (int kb = 0; kb < nblk; kb++) {
            float p0 = sc[kb][0], p1 = sc[kb][1], p2 = sc[kb][2], p3 = sc[kb][3];
            int src0 = (lane & ~3) + (c >> 1);
            int src1 = src0 + 2;
            float t0 = __shfl_sync(0xffffffffu, p0, src0);
            float t1 = __shfl_sync(0xffffffffu, p1, src0);
            float t2 = __shfl_sync(0xffffffffu, p2, src0);
            float t3 = __shfl_sync(0xffffffffu, p3, src0);
            float u0 = __shfl_sync(0xffffffffu, p0, src1);
            float u1 = __shfl_sync(0xffffffffu, p1, src1);
            float u2 = __shfl_sync(0xffffffffu, p2, src1);
            float u3 = __shfl_sync(0xffffffffu, p3, src1);
            unsigned ah[4], al[4];
            split_tf32((c & 1) ? t1 : t0, ah[0], al[0]);
            split_tf32((c & 1) ? t3 : t2, ah[1], al[1]);
            split_tf32((c & 1) ? u1 : u0, ah[2], al[2]);
            split_tf32((c & 1) ? u3 : u2, ah[3], al[3]);
#pragma unroll
            for (int nf2 = 0; nf2 < 8; nf2++) {
                unsigned bh[2], bl[2];
                bh[0] = __float_as_uint(Sh[kb * 8 + c    ][nf2 * 8 + g]);
                bh[1] = __float_as_uint(Sh[kb * 8 + c + 4][nf2 * 8 + g]);
                bl[0] = __float_as_uint(Sl[kb * 8 + c    ][nf2 * 8 + g]);
                bl[1] = __float_as_uint(Sl[kb * 8 + c + 4][nf2 * 8 + g]);
                mma3(oacc[nf2], ah, al, bh, bl);
            }
        }
        __syncthreads();   // done reading V before next K load
    }

    // finalize: quad-sum l, normalize, write pre-split output for Wo GEMM
    l0 += __shfl_xor_sync(0xffffffffu, l0, 1);
    l0 += __shfl_xor_sync(0xffffffffu, l0, 2);
    l1 += __shfl_xor_sync(0xffffffffu, l1, 1);
    l1 += __shfl_xor_sync(0xffffffffu, l1, 2);
    float inv0 = 1.0f / l0, inv1 = 1.0f / l1;

    size_t o0 = (size_t)(b * SEQ + qr0) * DMODEL + h * HDIM;
    size_t o1 = (size_t)(b * SEQ + qr1) * DMODEL + h * HDIM;
#pragma unroll
    for (int nf = 0; nf < 8; nf++) {
        int col = nf * 8 + 2 * c;
        unsigned hbits, lbits;
        float2 h2, l2;
        split_tf32(oacc[nf][0] * inv0, hbits, lbits); h2.x = __uint_as_float(hbits); l2.x = __uint_as_float(lbits);
        split_tf32(oacc[nf][1] * inv0, hbits, lbits); h2.y = __uint_as_float(hbits); l2.y = __uint_as_float(lbits);
        *(float2*)(oh + o0 + col) = h2; *(float2*)(ol + o0 + col) = l2;
        split_tf32(oacc[nf][2] * inv1, hbits, lbits); h2.x = __uint_as_float(hbits); l2.x = __uint_as_float(lbits);
        split_tf32(oacc[nf][3] * inv1, hbits, lbits); h2.y = __uint_as_float(hbits); l2.y = __uint_as_float(lbits);
        *(float2*)(oh + o1 + col) = h2; *(float2*)(ol + o1 + col) = l2;
    }
}

// ---------------- launch ----------------
extern "C" void kernel_launch(void* const* d_in, const int* in_sizes, int n_in,
                              void* d_out, int out_size) {
    const float* x  = (const float*)d_in[0];
    const float* Wq = (const float*)d_in[1];
    const float* Wk = (const float*)d_in[2];
    const float* Wv = (const float*)d_in[3];
    const float* Wo = (const float*)d_in[4];
    float* out = (float*)d_out;

    float *xh, *xl, *wh, *wl, *qraw, *kraw, *qh, *ql, *kh, *kl, *vh, *vl, *ath, *atl, *ct, *st;
    cudaGetSymbolAddress((void**)&xh,   g_xh);
    cudaGetSymbolAddress((void**)&xl,   g_xl);
    cudaGetSymbolAddress((void**)&wh,   g_wh);
    cudaGetSymbolAddress((void**)&wl,   g_wl);
    cudaGetSymbolAddress((void**)&qraw, g_qraw);
    cudaGetSymbolAddress((void**)&kraw, g_kraw);
    cudaGetSymbolAddress((void**)&qh,   g_qh);
    cudaGetSymbolAddress((void**)&ql,   g_ql);
    cudaGetSymbolAddress((void**)&kh,   g_kh);
    cudaGetSymbolAddress((void**)&kl,   g_kl);
    cudaGetSymbolAddress((void**)&vh,   g_vh);
    cudaGetSymbolAddress((void**)&vl,   g_vl);
    cudaGetSymbolAddress((void**)&ath,  g_ath);
    cudaGetSymbolAddress((void**)&atl,  g_atl);
    cudaGetSymbolAddress((void**)&ct,   g_cos);
    cudaGetSymbolAddress((void**)&st,   g_sin);

    // RoPE tables
    {
        int n = SEQ * (HDIM/2);
        rope_table_kernel<<<(n + 255) / 256, 256>>>(ct, st);
    }

    // prepass splits: x and weights
    split_kernel<<<(NELEM + 255) / 256, 256>>>(x,  xh, xl, NELEM);
    split_kernel<<<(WELEM + 255) / 256, 256>>>(Wq, wh + 0 * WELEM, wl + 0 * WELEM, WELEM);
    split_kernel<<<(WELEM + 255) / 256, 256>>>(Wk, wh + 1 * WELEM, wl + 1 * WELEM, WELEM);
    split_kernel<<<(WELEM + 255) / 256, 256>>>(Wv, wh + 2 * WELEM, wl + 2 * WELEM, WELEM);
    split_kernel<<<(WELEM + 255) / 256, 256>>>(Wo, wh + 3 * WELEM, wl + 3 * WELEM, WELEM);

    // merged QKV projection: z=0 -> q raw, z=1 -> k raw, z=2 -> v split
    dim3 qkv_grid(DMODEL / 128, MROWS / 128, 3);   // (6, 32, 3)
    gemm3_kernel<<<qkv_grid, 256>>>(xh, xl,
                                    wh + 0 * WELEM, wl + 0 * WELEM,
                                    wh + 1 * WELEM, wl + 1 * WELEM,
                                    wh + 2 * WELEM, wl + 2 * WELEM,
                                    qraw, kraw, vh, vl);

    // fused RoPE + split for q (scaled), k
    {
        int n = MROWS * NHEADS * 32;
        rope_split_kernel<<<(n + 255) / 256, 256>>>(qraw, kraw, ct, st, qh, ql, kh, kl);
    }

    // causal attention -> pre-split output
    attn3_kernel<<<dim3(SEQ / 64, NHEADS, BATCH), 128>>>(qh, ql, kh, kl, vh, vl, ath, atl);

    // output projection (z=0 path only)
    dim3 o_grid(DMODEL / 128, MROWS / 128, 1);
    gemm3_kernel<<<o_grid, 256>>>(ath, atl,
                                  wh + 3 * WELEM, wl + 3 * WELEM,
                                  wh + 3 * WELEM, wl + 3 * WELEM,
                                  wh + 3 * WELEM, wl + 3 * WELEM,
                                  out, out, out, out);
}

// round 5
// speedup vs baseline: 2.2203x; 1.0087x over previous
#include <cuda_runtime.h>
#include <cuda_bf16.h>
#include <math.h>

#define BATCH 2
#define SEQ   2048
#define DMODEL 768
#define NHEADS 12
#define HDIM  64
#define MROWS (BATCH*SEQ)   // 4096
#define NELEM (MROWS*DMODEL)
#define WELEM (DMODEL*DMODEL)

// ---------------- scratch (device globals; allocation-free) ----------------
__device__ float g_xh[NELEM], g_xl[NELEM];
__device__ float g_wh[4][WELEM], g_wl[4][WELEM];
__device__ float g_qraw[NELEM], g_kraw[NELEM];
__device__ float g_qh[NELEM], g_ql[NELEM];
__device__ float g_kh[NELEM], g_kl[NELEM];
__device__ float g_vh[NELEM], g_vl[NELEM];
__device__ float g_ath[NELEM], g_atl[NELEM];
__device__ float g_cos[SEQ * (HDIM/2)];
__device__ float g_sin[SEQ * (HDIM/2)];

// ---------------- tf32 helpers ----------------
__device__ __forceinline__ unsigned f2tf32(float x) {
    unsigned r;
    asm("cvt.rna.tf32.f32 %0, %1;\n" : "=r"(r) : "f"(x));
    return r;
}
__device__ __forceinline__ void split_tf32(float x, unsigned& hi, unsigned& lo) {
    hi = f2tf32(x);
    lo = f2tf32(x - __uint_as_float(hi));
}
__device__ __forceinline__ void split_store(float x, float* hp, float* lp) {
    unsigned h, l; split_tf32(x, h, l);
    *hp = __uint_as_float(h);
    *lp = __uint_as_float(l);
}

__device__ __forceinline__ void mma_tf32(float* d, const unsigned* a, const unsigned* b, const float* c) {
    asm volatile(
        "mma.sync.aligned.m16n8k8.row.col.f32.tf32.tf32.f32 "
        "{%0,%1,%2,%3}, {%4,%5,%6,%7}, {%8,%9}, {%10,%11,%12,%13};\n"
        : "=f"(d[0]), "=f"(d[1]), "=f"(d[2]), "=f"(d[3])
        : "r"(a[0]), "r"(a[1]), "r"(a[2]), "r"(a[3]),
          "r"(b[0]), "r"(b[1]),
          "f"(c[0]), "f"(c[1]), "f"(c[2]), "f"(c[3]));
}
__device__ __forceinline__ void mma3(float* d, const unsigned* ah, const unsigned* al,
                                     const unsigned* bh, const unsigned* bl) {
    mma_tf32(d, al, bh, d);
    mma_tf32(d, ah, bl, d);
    mma_tf32(d, ah, bh, d);
}

__device__ __forceinline__ void cp_async16(void* smem, const void* gmem) {
    unsigned s = (unsigned)__cvta_generic_to_shared(smem);
    asm volatile("cp.async.cg.shared.global [%0], [%1], 16;\n" :: "r"(s), "l"(gmem));
}
__device__ __forceinline__ void cp_commit() { asm volatile("cp.async.commit_group;\n"); }
template<int N> __device__ __forceinline__ void cp_wait() {
    asm volatile("cp.async.wait_group %0;\n" :: "n"(N));
}

// ---------------- prepass splits ----------------
__global__ void split_kernel(const float* __restrict__ src, float* __restrict__ hi,
                             float* __restrict__ lo, int n) {
    int i = blockIdx.x * blockDim.x + threadIdx.x;
    if (i >= n) return;
    split_store(src[i], hi + i, lo + i);
}
__global__ void split_w4_kernel(const float* __restrict__ a0, const float* __restrict__ a1,
                                const float* __restrict__ a2, const float* __restrict__ a3,
                                float* __restrict__ hi, float* __restrict__ lo) {
    int i = blockIdx.x * blockDim.x + threadIdx.x;
    if (i >= 4 * WELEM) return;
    int w = i / WELEM, j = i - w * WELEM;
    const float* src = (w == 0) ? a0 : (w == 1) ? a1 : (w == 2) ? a2 : a3;
    split_store(src[j], hi + i, lo + i);
}

// ---------------- RoPE table ----------------
__global__ void rope_table_kernel(float* ct, float* st) {
    int idx = blockIdx.x * blockDim.x + threadIdx.x;
    if (idx >= SEQ * (HDIM/2)) return;
    int t = idx >> 5;
    int i = idx & 31;
    float inv_freq = powf(10000.0f, -(float)(2 * i) / (float)HDIM);
    float ang = (float)t * inv_freq;
    ct[idx] = cosf(ang);
    st[idx] = sinf(ang);
}

// ---------------- fused RoPE + split (q gets 0.125 scale folded) ----------------
__global__ void rope_split_kernel(const float* __restrict__ q, const float* __restrict__ k,
                                  const float* __restrict__ ct, const float* __restrict__ st,
                                  float* qh, float* ql, float* kh, float* kl) {
    int idx = blockIdx.x * blockDim.x + threadIdx.x;
    if (idx >= MROWS * NHEADS * 32) return;
    int i   = idx & 31;
    int h   = (idx >> 5) % NHEADS;
    int row = idx / (32 * NHEADS);
    int t   = row % SEQ;
    float c = ct[t * 32 + i];
    float s = st[t * 32 + i];
    size_t base = (size_t)row * DMODEL + h * HDIM;
    float x1 = q[base + i], x2 = q[base + 32 + i];
    split_store((x1 * c - x2 * s) * 0.125f, qh + base + i,      ql + base + i);
    split_store((x1 * s + x2 * c) * 0.125f, qh + base + 32 + i, ql + base + 32 + i);
    x1 = k[base + i]; x2 = k[base + 32 + i];
    split_store(x1 * c - x2 * s, kh + base + i,      kl + base + i);
    split_store(x1 * s + x2 * c, kh + base + 32 + i, kl + base + 32 + i);
}

// ---------------- 3xtf32 GEMM on pre-split operands, K-chunk 16 ----------------
// C[4096,768] = A @ B. 128x128 tile, 256 threads, z selects B/C (merged QKV).
#define GA_OFF   0                 // Ah: 2*128*20
#define GAL_OFF  (2*128*20)        // Al
#define GB_OFF   (2*(2*128*20))    // Bh: 2*16*136
#define GBL_OFF  (GB_OFF + 2*16*136)
#define GEMM_SMEM ((GBL_OFF + 2*16*136) * 4)

__global__ __launch_bounds__(256)
void gemm3_kernel(const float* __restrict__ Ah, const float* __restrict__ Al,
                  const float* __restrict__ Bh0, const float* __restrict__ Bl0,
                  const float* __restrict__ Bh1, const float* __restrict__ Bl1,
                  const float* __restrict__ Bh2, const float* __restrict__ Bl2,
                  float* __restrict__ C0, float* __restrict__ C1,
                  float* __restrict__ C2h, float* __restrict__ C2l) {
    const int K = DMODEL, N = DMODEL;
    extern __shared__ float sm[];
    float* Ah_s = sm + GA_OFF;    // [buf][128][20]
    float* Al_s = sm + GAL_OFF;
    float* Bh_s = sm + GB_OFF;    // [buf][16][136]
    float* Bl_s = sm + GBL_OFF;

    int z = blockIdx.z;
    const float* Bh = (z == 0) ? Bh0 : (z == 1) ? Bh1 : Bh2;
    const float* Bl = (z == 0) ? Bl0 : (z == 1) ? Bl1 : Bl2;

    int tid  = threadIdx.x;
    int wid  = tid >> 5, lane = tid & 31;
    int g = lane >> 2, c = lane & 3;
    int wm = (wid & 3) * 32;
    int wn = (wid >> 2) * 64;
    int bm = blockIdx.y * 128, bn = blockIdx.x * 128;

    int arow = tid >> 1,  acol = (tid & 1) * 8;
    int brow = tid >> 4,  bcol = (tid & 15) * 8;

    float acc[2][8][4];
#pragma unroll
    for (int mf = 0; mf < 2; mf++)
#pragma unroll
        for (int nf = 0; nf < 8; nf++)
#pragma unroll
            for (int j = 0; j < 4; j++) acc[mf][nf][j] = 0.0f;

    auto load_chunk = [&](int buf, int k0) {
        size_t aoff = (size_t)(bm + arow) * K + k0 + acol;
        float* ah = Ah_s + buf * 2560 + arow * 20 + acol;
        float* al = Al_s + buf * 2560 + arow * 20 + acol;
        cp_async16(ah,     Ah + aoff);
        cp_async16(ah + 4, Ah + aoff + 4);
        cp_async16(al,     Al + aoff);
        cp_async16(al + 4, Al + aoff + 4);
        size_t boff = (size_t)(k0 + brow) * N + bn + bcol;
        float* bh = Bh_s + buf * 2176 + brow * 136 + bcol;
        float* bl = Bl_s + buf * 2176 + brow * 136 + bcol;
        cp_async16(bh,     Bh + boff);
        cp_async16(bh + 4, Bh + boff + 4);
        cp_async16(bl,     Bl + boff);
        cp_async16(bl + 4, Bl + boff + 4);
    };

    const int NCH = K / 16;  // 48
    load_chunk(0, 0); cp_commit();

    for (int ch = 0; ch < NCH; ch++) {
        int buf = ch & 1;
        if (ch + 1 < NCH) { load_chunk(buf ^ 1, (ch + 1) * 16); cp_commit(); cp_wait<1>(); }
        else              { cp_wait<0>(); }
        __syncthreads();

        const float* ahb = Ah_s + buf * 2560;
        const float* alb = Al_s + buf * 2560;
        const float* bhb = Bh_s + buf * 2176;
        const float* blb = Bl_s + buf * 2176;
#pragma unroll
        for (int ks = 0; ks < 2; ks++) {
            int k0 = ks * 8;
            unsigned afh[2][4], afl[2][4], bfh[8][2], bfl[8][2];
#pragma unroll
            for (int mf = 0; mf < 2; mf++) {
                int m0 = wm + mf * 16;
                afh[mf][0] = __float_as_uint(ahb[(m0 + g    ) * 20 + k0 + c    ]);
                afh[mf][1] = __float_as_uint(ahb[(m0 + g + 8) * 20 + k0 + c    ]);
                afh[mf][2] = __float_as_uint(ahb[(m0 + g    ) * 20 + k0 + c + 4]);
                afh[mf][3] = __float_as_uint(ahb[(m0 + g + 8) * 20 + k0 + c + 4]);
                afl[mf][0] = __float_as_uint(alb[(m0 + g    ) * 20 + k0 + c    ]);
                afl[mf][1] = __float_as_uint(alb[(m0 + g + 8) * 20 + k0 + c    ]);
                afl[mf][2] = __float_as_uint(alb[(m0 + g    ) * 20 + k0 + c + 4]);
                afl[mf][3] = __float_as_uint(alb[(m0 + g + 8) * 20 + k0 + c + 4]);
            }
#pragma unroll
            for (int nf = 0; nf < 8; nf++) {
                int n0 = wn + nf * 8 + g;
                bfh[nf][0] = __float_as_uint(bhb[(k0 + c    ) * 136 + n0]);
                bfh[nf][1] = __float_as_uint(bhb[(k0 + c + 4) * 136 + n0]);
                bfl[nf][0] = __float_as_uint(blb[(k0 + c    ) * 136 + n0]);
                bfl[nf][1] = __float_as_uint(blb[(k0 + c + 4) * 136 + n0]);
            }
#pragma unroll
            for (int mf = 0; mf < 2; mf++)
#pragma unroll
                for (int nf = 0; nf < 8; nf++)
                    mma3(acc[mf][nf], afh[mf], afl[mf], bfh[nf], bfl[nf]);
        }
        __syncthreads();
    }

#pragma unroll
    for (int mf = 0; mf < 2; mf++) {
        int row0 = bm + wm + mf * 16 + g;
#pragma unroll
        for (int nf = 0; nf < 8; nf++) {
            int col = bn + wn + nf * 8 + 2 * c;
            size_t o0 = (size_t)row0 * N + col;
            size_t o1 = (size_t)(row0 + 8) * N + col;
            if (z == 2) {
                unsigned hh, ll;
                float2 h0, l0, h1, l1;
                split_tf32(acc[mf][nf][0], hh, ll); h0.x = __uint_as_float(hh); l0.x = __uint_as_float(ll);
                split_tf32(acc[mf][nf][1], hh, ll); h0.y = __uint_as_float(hh); l0.y = __uint_as_float(ll);
                split_tf32(acc[mf][nf][2], hh, ll); h1.x = __uint_as_float(hh); l1.x = __uint_as_float(ll);
                split_tf32(acc[mf][nf][3], hh, ll); h1.y = __uint_as_float(hh); l1.y = __uint_as_float(ll);
                *(float2*)(C2h + o0) = h0; *(float2*)(C2l + o0) = l0;
                *(float2*)(C2h + o1) = h1; *(float2*)(C2l + o1) = l1;
            } else {
                float* C = (z == 0) ? C0 : C1;
                *(float2*)(C + o0) = make_float2(acc[mf][nf][0], acc[mf][nf][1]);
                *(float2*)(C + o1) = make_float2(acc[mf][nf][2], acc[mf][nf][3]);
            }
        }
    }
}

// ---------------- pipelined 3xtf32 causal flash attention ----------------
// grid: (SEQ/128, NHEADS, BATCH), 256 threads (8 warps), 16 q-rows per warp.
// K and V tiles each double-buffered (hi+lo), 144KB dynamic smem.
#define TSZ (64*72)
#define ATTN_SMEM (8 * TSZ * 4)

__global__ __launch_bounds__(256, 1)
void attn3_kernel(const float* __restrict__ qh, const float* __restrict__ ql,
                  const float* __restrict__ kh, const float* __restrict__ kl,
                  const float* __restrict__ vh, const float* __restrict__ vl,
                  float* __restrict__ oh, float* __restrict__ ol) {
    extern __shared__ float sm[];
    // layout: KH0 KH1 KL0 KL1 VH0 VH1 VL0 VL1

    int qt = blockIdx.x, h = blockIdx.y, b = blockIdx.z;
    int tid = threadIdx.x;
    int warp = tid >> 5, lane = tid & 31;
    int g = lane >> 2, c = lane & 3;
    int qbase_w = qt * 128 + warp * 16;

    // Q fragments from pre-split, pre-scaled arrays
    unsigned qah[8][4], qal[8][4];
    {
        size_t qb = (size_t)(b * SEQ + qbase_w) * DMODEL + h * HDIM;
#pragma unroll
        for (int ks = 0; ks < 8; ks++) {
            size_t i00 = qb + (size_t)g * DMODEL       + ks * 8 + c;
            size_t i10 = qb + (size_t)(g + 8) * DMODEL + ks * 8 + c;
            qah[ks][0] = __float_as_uint(qh[i00]);
            qah[ks][1] = __float_as_uint(qh[i10]);
            qah[ks][2] = __float_as_uint(qh[i00 + 4]);
            qah[ks][3] = __float_as_uint(qh[i10 + 4]);
            qal[ks][0] = __float_as_uint(ql[i00]);
            qal[ks][1] = __float_as_uint(ql[i10]);
            qal[ks][2] = __float_as_uint(ql[i00 + 4]);
            qal[ks][3] = __float_as_uint(ql[i10 + 4]);
        }
    }

    float oacc[8][4];
#pragma unroll
    for (int nf = 0; nf < 8; nf++)
#pragma unroll
        for (int j = 0; j < 4; j++) oacc[nf][j] = 0.0f;
    float m0 = -1e30f, m1 = -1e30f, l0 = 0.0f, l1 = 0.0f;
    int qr0 = qbase_w + g;
    int qr1 = qr0 + 8;

    auto load_kv = [&](int buf, int kt) {
        size_t tb = (size_t)(b * SEQ + kt * 64) * DMODEL + h * HDIM;
        float* dkh = sm + buf * TSZ;
        float* dkl = sm + (2 + buf) * TSZ;
        float* dvh = sm + (4 + buf) * TSZ;
        float* dvl = sm + (6 + buf) * TSZ;
#pragma unroll
        for (int i = tid; i < 64 * 16; i += 256) {
            int row = i >> 4, c4 = (i & 15) * 4;
            size_t off = tb + (size_t)row * DMODEL + c4;
            int so = row * 72 + c4;
            cp_async16(dkh + so, kh + off);
            cp_async16(dkl + so, kl + off);
            cp_async16(dvh + so, vh + off);
            cp_async16(dvl + so, vl + off);
        }
    };

    const int kt_max = 2 * qt + 1;
    load_kv(0, 0); cp_commit();

    for (int kt = 0; kt <= kt_max; kt++) {
        int buf = kt & 1;
        if (kt < kt_max) { load_kv(buf ^ 1, kt + 1); cp_commit(); cp_wait<1>(); }
        else             { cp_wait<0>(); }
        __syncthreads();   // tile kt visible to all warps

        // per-warp valid 8-key blocks in this tile
        int rel = qbase_w + 15 - kt * 64;
        int nblk = (rel < 0) ? 0 : min(8, (rel >> 3) + 1);
        bool need_mask = (kt * 64 + 63 > qbase_w);

        if (nblk > 0) {
            const float* ksh = sm + buf * TSZ;
            const float* ksl = sm + (2 + buf) * TSZ;

            // S = Q K^T
            float sc[8][4];
            for (int nf = 0; nf < nblk; nf++) {
#pragma unroll
                for (int j = 0; j < 4; j++) sc[nf][j] = 0.0f;
#pragma unroll
                for (int ks = 0; ks < 8; ks++) {
                    unsigned bh[2], bl[2];
                    bh[0] = __float_as_uint(ksh[(nf * 8 + g) * 72 + ks * 8 + c    ]);
                    bh[1] = __float_as_uint(ksh[(nf * 8 + g) * 72 + ks * 8 + c + 4]);
                    bl[0] = __float_as_uint(ksl[(nf * 8 + g) * 72 + ks * 8 + c    ]);
                    bl[1] = __float_as_uint(ksl[(nf * 8 + g) * 72 + ks * 8 + c + 4]);
                    mma3(sc[nf], qah[ks], qal[ks], bh, bl);
                }
            }

            if (need_mask) {
                for (int nf = 0; nf < nblk; nf++) {
#pragma unroll
                    for (int j = 0; j < 4; j++) {
                        int key = kt * 64 + nf * 8 + 2 * c + (j & 1);
                        int qr  = (j < 2) ? qr0 : qr1;
                        if (key > qr) sc[nf][j] = -1e30f;
                    }
                }
            }

            // online softmax
            float mx0 = -1e30f, mx1 = -1e30f;
            for (int nf = 0; nf < nblk; nf++) {
                mx0 = fmaxf(mx0, fmaxf(sc[nf][0], sc[nf][1]));
                mx1 = fmaxf(mx1, fmaxf(sc[nf][2], sc[nf][3]));
            }
            mx0 = fmaxf(mx0, __shfl_xor_sync(0xffffffffu, mx0, 1));
            mx0 = fmaxf(mx0, __shfl_xor_sync(0xffffffffu, mx0, 2));
            mx1 = fmaxf(mx1, __shfl_xor_sync(0xffffffffu, mx1, 1));
            mx1 = fmaxf(mx1, __shfl_xor_sync(0xffffffffu, mx1, 2));
            float nm0 = fmaxf(m0, mx0), nm1 = fmaxf(m1, mx1);
            float cor0 = __expf(m0 - nm0), cor1 = __expf(m1 - nm1);
            m0 = nm0; m1 = nm1;
            l0 *= cor0; l1 *= cor1;
#pragma unroll
            for (int nf = 0; nf < 8; nf++) {
                oacc[nf][0] *= cor0; oacc[nf][1] *= cor0;
                oacc[nf][2] *= cor1; oacc[nf][3] *= cor1;
            }
            for (int nf = 0; nf < nblk; nf++) {
                sc[nf][0] = __expf(sc[nf][0] - m0);
                sc[nf][1] = __expf(sc[nf][1] - m0);
                sc[nf][2] = __expf(sc[nf][2] - m1);
                sc[nf][3] = __expf(sc[nf][3] - m1);
                l0 += sc[nf][0] + sc[nf][1];
                l1 += sc[nf][2] + sc[nf][3];
            }

            // O += P V
            const float* vsh = sm + (4 + buf) * TSZ;
            const float* vsl = sm + (6 + buf) * TSZ;
            for (int kb = 0; kb < nblk; kb++) {
                float p0 = sc[kb][0], p1 = sc[kb][1], p2 = sc[kb][2], p3 = sc[kb][3];
                int src0 = (lane & ~3) + (c >> 1);
                int src1 = src0 + 2;
                float t0 = __shfl_sync(0xffffffffu, p0, src0);
                float t1 = __shfl_sync(0xffffffffu, p1, src0);
                float t2 = __shfl_sync(0xffffffffu, p2, src0);
                float t3 = __shfl_sync(0xffffffffu, p3, src0);
                float u0 = __shfl_sync(0xffffffffu, p0, src1);
                float u1 = __shfl_sync(0xffffffffu, p1, src1);
                float u2 = __shfl_sync(0xffffffffu, p2, src1);
                float u3 = __shfl_sync(0xffffffffu, p3, src1);
                unsigned ah[4], al[4];
                split_tf32((c & 1) ? t1 : t0, ah[0], al[0]);
                split_tf32((c & 1) ? t3 : t2, ah[1], al[1]);
                split_tf32((c & 1) ? u1 : u0, ah[2], al[2]);
                split_tf32((c & 1) ? u3 : u2, ah[3], al[3]);
#pragma unroll
                for (int nf2 = 0; nf2 < 8; nf2++) {
                    unsigned bh[2], bl[2];
                    bh[0] = __float_as_uint(vsh[(kb * 8 + c    ) * 72 + nf2 * 8 + g]);
                    bh[1] = __float_as_uint(vsh[(kb * 8 + c + 4) * 72 + nf2 * 8 + g]);
                    bl[0] = __float_as_uint(vsl[(kb * 8 + c    ) * 72 + nf2 * 8 + g]);
                    bl[1] = __float_as_uint(vsl[(kb * 8 + c + 4) * 72 + nf2 * 8 + g]);
                    mma3(oacc[nf2], ah, al, bh, bl);
                }
            }
        }
        __syncthreads();   // all warps done reading buffers before next issue
    }

    // finalize
    l0 += __shfl_xor_sync(0xffffffffu, l0, 1);
    l0 += __shfl_xor_sync(0xffffffffu, l0, 2);
    l1 += __shfl_xor_sync(0xffffffffu, l1, 1);
    l1 += __shfl_xor_sync(0xffffffffu, l1, 2);
    float inv0 = 1.0f / l0, inv1 = 1.0f / l1;

    size_t o0 = (size_t)(b * SEQ + qr0) * DMODEL + h * HDIM;
    size_t o1 = (size_t)(b * SEQ + qr1) * DMODEL + h * HDIM;
#pragma unroll
    for (int nf = 0; nf < 8; nf++) {
        int col = nf * 8 + 2 * c;
        unsigned hbits, lbits;
        float2 h2, l2;
        split_tf32(oacc[nf][0] * inv0, hbits, lbits); h2.x = __uint_as_float(hbits); l2.x = __uint_as_float(lbits);
        split_tf32(oacc[nf][1] * inv0, hbits, lbits); h2.y = __uint_as_float(hbits); l2.y = __uint_as_float(lbits);
        *(float2*)(oh + o0 + col) = h2; *(float2*)(ol + o0 + col) = l2;
        split_tf32(oacc[nf][2] * inv1, hbits, lbits); h2.x = __uint_as_float(hbits); l2.x = __uint_as_float(lbits);
        split_tf32(oacc[nf][3] * inv1, hbits, lbits); h2.y = __uint_as_float(hbits); l2.y = __uint_as_float(lbits);
        *(float2*)(oh + o1 + col) = h2; *(float2*)(ol + o1 + col) = l2;
    }
}

// ---------------- launch ----------------
extern "C" void kernel_launch(void* const* d_in, const int* in_sizes, int n_in,
                              void* d_out, int out_size) {
    const float* x  = (const float*)d_in[0];
    const float* Wq = (const float*)d_in[1];
    const float* Wk = (const float*)d_in[2];
    const float* Wv = (const float*)d_in[3];
    const float* Wo = (const float*)d_in[4];
    float* out = (float*)d_out;

    cudaFuncSetAttribute(gemm3_kernel, cudaFuncAttributeMaxDynamicSharedMemorySize, GEMM_SMEM);
    cudaFuncSetAttribute(attn3_kernel, cudaFuncAttributeMaxDynamicSharedMemorySize, ATTN_SMEM);

    float *xh, *xl, *wh, *wl, *qraw, *kraw, *qh, *ql, *kh, *kl, *vh, *vl, *ath, *atl, *ct, *st;
    cudaGetSymbolAddress((void**)&xh,   g_xh);
    cudaGetSymbolAddress((void**)&xl,   g_xl);
    cudaGetSymbolAddress((void**)&wh,   g_wh);
    cudaGetSymbolAddress((void**)&wl,   g_wl);
    cudaGetSymbolAddress((void**)&qraw, g_qraw);
    cudaGetSymbolAddress((void**)&kraw, g_kraw);
    cudaGetSymbolAddress((void**)&qh,   g_qh);
    cudaGetSymbolAddress((void**)&ql,   g_ql);
    cudaGetSymbolAddress((void**)&kh,   g_kh);
    cudaGetSymbolAddress((void**)&kl,   g_kl);
    cudaGetSymbolAddress((void**)&vh,   g_vh);
    cudaGetSymbolAddress((void**)&vl,   g_vl);
    cudaGetSymbolAddress((void**)&ath,  g_ath);
    cudaGetSymbolAddress((void**)&atl,  g_atl);
    cudaGetSymbolAddress((void**)&ct,   g_cos);
    cudaGetSymbolAddress((void**)&st,   g_sin);

    {
        int n = SEQ * (HDIM/2);
        rope_table_kernel<<<(n + 255) / 256, 256>>>(ct, st);
    }

    split_kernel<<<(NELEM + 255) / 256, 256>>>(x, xh, xl, NELEM);
    split_w4_kernel<<<(4 * WELEM + 255) / 256, 256>>>(Wq, Wk, Wv, Wo, wh, wl);

    // merged QKV projection: z=0 -> q raw, z=1 -> k raw, z=2 -> v split
    dim3 qkv_grid(DMODEL / 128, MROWS / 128, 3);
    gemm3_kernel<<<qkv_grid, 256, GEMM_SMEM>>>(xh, xl,
                                    wh + 0 * WELEM, wl + 0 * WELEM,
                                    wh + 1 * WELEM, wl + 1 * WELEM,
                                    wh + 2 * WELEM, wl + 2 * WELEM,
                                    qraw, kraw, vh, vl);

    {
        int n = MROWS * NHEADS * 32;
        rope_split_kernel<<<(n + 255) / 256, 256>>>(qraw, kraw, ct, st, qh, ql, kh, kl);
    }

    attn3_kernel<<<dim3(SEQ / 128, NHEADS, BATCH), 256, ATTN_SMEM>>>(qh, ql, kh, kl, vh, vl, ath, atl);

    dim3 o_grid(DMODEL / 128, MROWS / 128, 1);
    gemm3_kernel<<<o_grid, 256, GEMM_SMEM>>>(ath, atl,
                                  wh + 3 * WELEM, wl + 3 * WELEM,
                                  wh + 3 * WELEM, wl + 3 * WELEM,
                                  wh + 3 * WELEM, wl + 3 * WELEM,
                                  out, out, out, out);
}

// round 6
// speedup vs baseline: 3.9531x; 1.7804x over previous
#include <cuda_runtime.h>
#include <cuda_fp16.h>
#include <math.h>

#define BATCH 2
#define SEQ   2048
#define DMODEL 768
#define NHEADS 12
#define HDIM  64
#define MROWS (BATCH*SEQ)   // 4096
#define NELEM (MROWS*DMODEL)
#define WELEM (DMODEL*DMODEL)

// ---------------- scratch (device globals; allocation-free) ----------------
__device__ __half g_xh[NELEM],  g_xl[NELEM];
__device__ __half g_wth[4][WELEM], g_wtl[4][WELEM];   // transposed [n][k]
__device__ float  g_qraw[NELEM], g_kraw[NELEM], g_vraw[NELEM];
__device__ __half g_qh[NELEM], g_ql[NELEM];
__device__ __half g_kh[NELEM], g_kl[NELEM];
__device__ __half g_vth[NELEM], g_vtl[NELEM];          // [b][dglobal][t]
__device__ __half g_ath[NELEM], g_atl[NELEM];
__device__ float  g_cos[SEQ * (HDIM/2)];
__device__ float  g_sin[SEQ * (HDIM/2)];

// ---------------- fp16-split helpers ----------------
__device__ __forceinline__ void split_h(float x, __half& h, __half& l) {
    h = __float2half_rn(x);
    l = __float2half_rn(x - __half2float(h));
}
__device__ __forceinline__ unsigned pack2(__half a, __half b) {
    __half2 t = __halves2half2(a, b);
    return *(unsigned*)&t;
}
__device__ __forceinline__ void mma_f16(float* d, const unsigned* a, const unsigned* b, const float* c) {
    asm volatile(
        "mma.sync.aligned.m16n8k16.row.col.f32.f16.f16.f32 "
        "{%0,%1,%2,%3}, {%4,%5,%6,%7}, {%8,%9}, {%10,%11,%12,%13};\n"
        : "=f"(d[0]), "=f"(d[1]), "=f"(d[2]), "=f"(d[3])
        : "r"(a[0]), "r"(a[1]), "r"(a[2]), "r"(a[3]),
          "r"(b[0]), "r"(b[1]),
          "f"(c[0]), "f"(c[1]), "f"(c[2]), "f"(c[3]));
}
__device__ __forceinline__ void mma3h(float* d, const unsigned* ah, const unsigned* al,
                                      const unsigned* bh, const unsigned* bl) {
    mma_f16(d, al, bh, d);
    mma_f16(d, ah, bl, d);
    mma_f16(d, ah, bh, d);
}

__device__ __forceinline__ void cp_async16(void* smem, const void* gmem) {
    unsigned s = (unsigned)__cvta_generic_to_shared(smem);
    asm volatile("cp.async.cg.shared.global [%0], [%1], 16;\n" :: "r"(s), "l"(gmem));
}
__device__ __forceinline__ void cp_commit() { asm volatile("cp.async.commit_group;\n"); }
template<int N> __device__ __forceinline__ void cp_wait() {
    asm volatile("cp.async.wait_group %0;\n" :: "n"(N));
}

// ---------------- prepass: x split (natural layout) ----------------
__global__ void split_x_kernel(const float* __restrict__ src, __half* __restrict__ hi,
                               __half* __restrict__ lo, int n) {
    int i = blockIdx.x * blockDim.x + threadIdx.x;
    if (i >= n) return;
    split_h(src[i], hi[i], lo[i]);
}

// ---------------- prepass: weight transpose + split -> Wt[n][k] ----------------
__global__ void wtrans_kernel(const float* __restrict__ w0, const float* __restrict__ w1,
                              const float* __restrict__ w2, const float* __restrict__ w3,
                              __half* __restrict__ hi, __half* __restrict__ lo) {
    __shared__ float t[32][33];
    int w = blockIdx.z;
    const float* W = (w == 0) ? w0 : (w == 1) ? w1 : (w == 2) ? w2 : w3;
    int k0 = blockIdx.x * 32, n0 = blockIdx.y * 32;
    int tx = threadIdx.x, ty = threadIdx.y;
    t[ty][tx] = W[(size_t)(k0 + ty) * DMODEL + n0 + tx];
    __syncthreads();
    float v = t[tx][ty];   // = W[k0+tx][n0+ty]
    size_t o = (size_t)w * WELEM + (size_t)(n0 + ty) * DMODEL + k0 + tx;
    split_h(v, hi[o], lo[o]);
}

// ---------------- prepass: V transpose + split -> vt[b][dglobal][t] ----------------
__global__ void vtrans_kernel(const float* __restrict__ vraw,
                              __half* __restrict__ hi, __half* __restrict__ lo) {
    __shared__ float t[32][33];
    int b = blockIdx.z;
    int t0 = blockIdx.x * 32, d0 = blockIdx.y * 32;
    int tx = threadIdx.x, ty = threadIdx.y;
    t[ty][tx] = vraw[(size_t)(b * SEQ + t0 + ty) * DMODEL + d0 + tx];
    __syncthreads();
    float v = t[tx][ty];   // = vraw[t0+tx][d0+ty]
    size_t o = ((size_t)b * DMODEL + d0 + ty) * SEQ + t0 + tx;
    split_h(v, hi[o], lo[o]);
}

// ---------------- RoPE table ----------------
__global__ void rope_table_kernel(float* ct, float* st) {
    int idx = blockIdx.x * blockDim.x + threadIdx.x;
    if (idx >= SEQ * (HDIM/2)) return;
    int t = idx >> 5;
    int i = idx & 31;
    float inv_freq = powf(10000.0f, -(float)(2 * i) / (float)HDIM);
    float ang = (float)t * inv_freq;
    ct[idx] = cosf(ang);
    st[idx] = sinf(ang);
}

// ---------------- fused RoPE + fp16 split (q scaled by 0.125) ----------------
__global__ void rope_split_kernel(const float* __restrict__ q, const float* __restrict__ k,
                                  const float* __restrict__ ct, const float* __restrict__ st,
                                  __half* qh, __half* ql, __half* kh, __half* kl) {
    int idx = blockIdx.x * blockDim.x + threadIdx.x;
    if (idx >= MROWS * NHEADS * 32) return;
    int i   = idx & 31;
    int h   = (idx >> 5) % NHEADS;
    int row = idx / (32 * NHEADS);
    int t   = row % SEQ;
    float c = ct[t * 32 + i];
    float s = st[t * 32 + i];
    size_t base = (size_t)row * DMODEL + h * HDIM;
    float x1 = q[base + i], x2 = q[base + 32 + i];
    split_h((x1 * c - x2 * s) * 0.125f, qh[base + i],      ql[base + i]);
    split_h((x1 * s + x2 * c) * 0.125f, qh[base + 32 + i], ql[base + 32 + i]);
    x1 = k[base + i]; x2 = k[base + 32 + i];
    split_h(x1 * c - x2 * s, kh[base + i],      kl[base + i]);
    split_h(x1 * s + x2 * c, kh[base + 32 + i], kl[base + 32 + i]);
}

// ---------------- 3xFP16 GEMM: C[4096,768] = A[4096,768] @ B ----------------
// A pre-split [m][k] halves; B pre-split transposed [n][k] halves.
// 128x128 tile, BK=32, 256 threads (8 warps, 4x2), warp 32x64. z selects B/C.
#define GEMM_SMEM 81920   // 4 arrays * 2 bufs * 128*40 halves * 2B

__global__ __launch_bounds__(256, 2)
void gemm_f16_kernel(const __half* __restrict__ Ah, const __half* __restrict__ Al,
                     const __half* __restrict__ B0h, const __half* __restrict__ B0l,
                     const __half* __restrict__ B1h, const __half* __restrict__ B1l,
                     const __half* __restrict__ B2h, const __half* __restrict__ B2l,
                     float* __restrict__ C0, float* __restrict__ C1, float* __restrict__ C2) {
    const int K = DMODEL, N = DMODEL;
    extern __shared__ __half smh[];
    __half* As_h = smh;            // [2][128][40]
    __half* As_l = smh + 10240;
    __half* Bs_h = smh + 20480;    // [2][128][40]  (n-major)
    __half* Bs_l = smh + 30720;

    int z = blockIdx.z;
    const __half* Bh = (z == 0) ? B0h : (z == 1) ? B1h : B2h;
    const __half* Bl = (z == 0) ? B0l : (z == 1) ? B1l : B2l;
    float* C = (z == 0) ? C0 : (z == 1) ? C1 : C2;

    int tid  = threadIdx.x;
    int wid  = tid >> 5, lane = tid & 31;
    int g = lane >> 2, c = lane & 3;
    int wm = (wid & 3) * 32;
    int wn = (wid >> 2) * 64;
    int bm = blockIdx.y * 128, bn = blockIdx.x * 128;

    int lrow = tid >> 1, lseg = (tid & 1) * 16;   // halves within a 32-half row

    float acc[2][8][4];
#pragma unroll
    for (int mf = 0; mf < 2; mf++)
#pragma unroll
        for (int nf = 0; nf < 8; nf++)
#pragma unroll
            for (int j = 0; j < 4; j++) acc[mf][nf][j] = 0.0f;

    auto load_chunk = [&](int buf, int k0) {
        size_t ga = (size_t)(bm + lrow) * K + k0 + lseg;
        __half* da_h = As_h + buf * 5120 + lrow * 40 + lseg;
        __half* da_l = As_l + buf * 5120 + lrow * 40 + lseg;
        cp_async16(da_h,     Ah + ga);
        cp_async16(da_h + 8, Ah + ga + 8);
        cp_async16(da_l,     Al + ga);
        cp_async16(da_l + 8, Al + ga + 8);
        size_t gb = (size_t)(bn + lrow) * K + k0 + lseg;
        __half* db_h = Bs_h + buf * 5120 + lrow * 40 + lseg;
        __half* db_l = Bs_l + buf * 5120 + lrow * 40 + lseg;
        cp_async16(db_h,     Bh + gb);
        cp_async16(db_h + 8, Bh + gb + 8);
        cp_async16(db_l,     Bl + gb);
        cp_async16(db_l + 8, Bl + gb + 8);
    };

    const int NCH = K / 32;  // 24
    load_chunk(0, 0); cp_commit();

    for (int ch = 0; ch < NCH; ch++) {
        int buf = ch & 1;
        if (ch + 1 < NCH) { load_chunk(buf ^ 1, (ch + 1) * 32); cp_commit(); cp_wait<1>(); }
        else              { cp_wait<0>(); }
        __syncthreads();

        const __half* ahb = As_h + buf * 5120;
        const __half* alb = As_l + buf * 5120;
        const __half* bhb = Bs_h + buf * 5120;
        const __half* blb = Bs_l + buf * 5120;
#pragma unroll
        for (int ks = 0; ks < 2; ks++) {
            int k0 = ks * 16;
            unsigned afh[2][4], afl[2][4], bfh[8][2], bfl[8][2];
#pragma unroll
            for (int mf = 0; mf < 2; mf++) {
                int m0 = wm + mf * 16;
                afh[mf][0] = *(const unsigned*)&ahb[(m0 + g    ) * 40 + k0 + 2 * c    ];
                afh[mf][1] = *(const unsigned*)&ahb[(m0 + g + 8) * 40 + k0 + 2 * c    ];
                afh[mf][2] = *(const unsigned*)&ahb[(m0 + g    ) * 40 + k0 + 2 * c + 8];
                afh[mf][3] = *(const unsigned*)&ahb[(m0 + g + 8) * 40 + k0 + 2 * c + 8];
                afl[mf][0] = *(const unsigned*)&alb[(m0 + g    ) * 40 + k0 + 2 * c    ];
                afl[mf][1] = *(const unsigned*)&alb[(m0 + g + 8) * 40 + k0 + 2 * c    ];
                afl[mf][2] = *(const unsigned*)&alb[(m0 + g    ) * 40 + k0 + 2 * c + 8];
                afl[mf][3] = *(const unsigned*)&alb[(m0 + g + 8) * 40 + k0 + 2 * c + 8];
            }
#pragma unroll
            for (int nf = 0; nf < 8; nf++) {
                int n0 = wn + nf * 8 + g;
                bfh[nf][0] = *(const unsigned*)&bhb[n0 * 40 + k0 + 2 * c    ];
                bfh[nf][1] = *(const unsigned*)&bhb[n0 * 40 + k0 + 2 * c + 8];
                bfl[nf][0] = *(const unsigned*)&blb[n0 * 40 + k0 + 2 * c    ];
                bfl[nf][1] = *(const unsigned*)&blb[n0 * 40 + k0 + 2 * c + 8];
            }
#pragma unroll
            for (int mf = 0; mf < 2; mf++)
#pragma unroll
                for (int nf = 0; nf < 8; nf++)
                    mma3h(acc[mf][nf], afh[mf], afl[mf], bfh[nf], bfl[nf]);
        }
        __syncthreads();
    }

#pragma unroll
    for (int mf = 0; mf < 2; mf++) {
        int row0 = bm + wm + mf * 16 + g;
#pragma unroll
        for (int nf = 0; nf < 8; nf++) {
            int col = bn + wn + nf * 8 + 2 * c;
            *(float2*)(C + (size_t)row0 * N + col)       = make_float2(acc[mf][nf][0], acc[mf][nf][1]);
            *(float2*)(C + (size_t)(row0 + 8) * N + col) = make_float2(acc[mf][nf][2], acc[mf][nf][3]);
        }
    }
}

// ---------------- 3xFP16 causal flash attention ----------------
// grid: (SEQ/128, NHEADS, BATCH), 256 threads (8 warps), 16 q-rows/warp.
// K tiles [key][d] (natural), V tiles [d][key] (from pre-transposed vt).
#define HTSZ (64 * 72)                 // halves per tile
#define ATTN_SMEM (8 * HTSZ * 2)       // 73728 B

__global__ __launch_bounds__(256, 1)
void attn_f16_kernel(const __half* __restrict__ qh, const __half* __restrict__ ql,
                     const __half* __restrict__ kh, const __half* __restrict__ kl,
                     const __half* __restrict__ vth, const __half* __restrict__ vtl,
                     __half* __restrict__ oh, __half* __restrict__ ol) {
    extern __shared__ __half sm[];
    // layout (halves): KH[2] | KL[2] | VH[2] | VL[2], each tile HTSZ

    int qt = blockIdx.x, h = blockIdx.y, b = blockIdx.z;
    int tid = threadIdx.x;
    int warp = tid >> 5, lane = tid & 31;
    int g = lane >> 2, c = lane & 3;
    int qbase_w = qt * 128 + warp * 16;

    // Q fragments (A operand, m16n8k16), 4 ks-steps over d=64
    unsigned qfh[4][4], qfl[4][4];
    {
        size_t b0 = (size_t)(b * SEQ + qbase_w + g)     * DMODEL + h * HDIM;
        size_t b1 = (size_t)(b * SEQ + qbase_w + g + 8) * DMODEL + h * HDIM;
#pragma unroll
        for (int ks = 0; ks < 4; ks++) {
            int k0 = ks * 16 + 2 * c;
            qfh[ks][0] = *(const unsigned*)&qh[b0 + k0];
            qfh[ks][1] = *(const unsigned*)&qh[b1 + k0];
            qfh[ks][2] = *(const unsigned*)&qh[b0 + k0 + 8];
            qfh[ks][3] = *(const unsigned*)&qh[b1 + k0 + 8];
            qfl[ks][0] = *(const unsigned*)&ql[b0 + k0];
            qfl[ks][1] = *(const unsigned*)&ql[b1 + k0];
            qfl[ks][2] = *(const unsigned*)&ql[b0 + k0 + 8];
            qfl[ks][3] = *(const unsigned*)&ql[b1 + k0 + 8];
        }
    }

    float oacc[8][4];
#pragma unroll
    for (int nf = 0; nf < 8; nf++)
#pragma unroll
        for (int j = 0; j < 4; j++) oacc[nf][j] = 0.0f;
    float m0 = -1e30f, m1 = -1e30f, l0 = 0.0f, l1 = 0.0f;
    int qr0 = qbase_w + g;
    int qr1 = qr0 + 8;

    auto load_kv = [&](int buf, int kt) {
        size_t kb_ = (size_t)(b * SEQ + kt * 64) * DMODEL + h * HDIM;
        size_t vb_ = ((size_t)b * DMODEL + h * HDIM) * SEQ + kt * 64;
        __half* dkh = sm + buf * HTSZ;
        __half* dkl = sm + (2 + buf) * HTSZ;
        __half* dvh = sm + (4 + buf) * HTSZ;
        __half* dvl = sm + (6 + buf) * HTSZ;
#pragma unroll
        for (int i = tid; i < 64 * 8; i += 256) {
            int row = i >> 3, seg = (i & 7) * 8;
            int so = row * 72 + seg;
            cp_async16(dkh + so, kh  + kb_ + (size_t)row * DMODEL + seg);
            cp_async16(dkl + so, kl  + kb_ + (size_t)row * DMODEL + seg);
            cp_async16(dvh + so, vth + vb_ + (size_t)row * SEQ    + seg);
            cp_async16(dvl + so, vtl + vb_ + (size_t)row * SEQ    + seg);
        }
    };

    const int kt_max = 2 * qt + 1;
    load_kv(0, 0); cp_commit();

    for (int kt = 0; kt <= kt_max; kt++) {
        int buf = kt & 1;
        if (kt < kt_max) { load_kv(buf ^ 1, kt + 1); cp_commit(); cp_wait<1>(); }
        else             { cp_wait<0>(); }
        __syncthreads();

        int rel = qbase_w + 15 - kt * 64;
        int nblk = (rel < 0) ? 0 : min(8, (rel >> 3) + 1);
        int nblkS = (nblk + 1) & ~1;            // round up to even (pairs of 8 for k16 PV)
        bool need_mask = (kt * 64 + 63 > qbase_w);

        if (nblkS > 0) {
            const __half* ksh = sm + buf * HTSZ;
            const __half* ksl = sm + (2 + buf) * HTSZ;

            // S = Q K^T
            float sc[8][4];
            for (int nf = 0; nf < nblkS; nf++) {
#pragma unroll
                for (int j = 0; j < 4; j++) sc[nf][j] = 0.0f;
#pragma unroll
                for (int ks = 0; ks < 4; ks++) {
                    int koff = ks * 16 + 2 * c;
                    unsigned bh[2], bl[2];
                    bh[0] = *(const unsigned*)&ksh[(nf * 8 + g) * 72 + koff    ];
                    bh[1] = *(const unsigned*)&ksh[(nf * 8 + g) * 72 + koff + 8];
                    bl[0] = *(const unsigned*)&ksl[(nf * 8 + g) * 72 + koff    ];
                    bl[1] = *(const unsigned*)&ksl[(nf * 8 + g) * 72 + koff + 8];
                    mma3h(sc[nf], qfh[ks], qfl[ks], bh, bl);
                }
            }

            if (need_mask) {
                for (int nf = 0; nf < nblkS; nf++) {
#pragma unroll
                    for (int j = 0; j < 4; j++) {
                        int key = kt * 64 + nf * 8 + 2 * c + (j & 1);
                        int qr  = (j < 2) ? qr0 : qr1;
                        if (key > qr) sc[nf][j] = -1e30f;
                    }
                }
            }

            // online softmax
            float mx0 = -1e30f, mx1 = -1e30f;
            for (int nf = 0; nf < nblkS; nf++) {
                mx0 = fmaxf(mx0, fmaxf(sc[nf][0], sc[nf][1]));
                mx1 = fmaxf(mx1, fmaxf(sc[nf][2], sc[nf][3]));
            }
            mx0 = fmaxf(mx0, __shfl_xor_sync(0xffffffffu, mx0, 1));
            mx0 = fmaxf(mx0, __shfl_xor_sync(0xffffffffu, mx0, 2));
            mx1 = fmaxf(mx1, __shfl_xor_sync(0xffffffffu, mx1, 1));
            mx1 = fmaxf(mx1, __shfl_xor_sync(0xffffffffu, mx1, 2));
            float nm0 = fmaxf(m0, mx0), nm1 = fmaxf(m1, mx1);
            float cor0 = __expf(m0 - nm0), cor1 = __expf(m1 - nm1);
            m0 = nm0; m1 = nm1;
            l0 *= cor0; l1 *= cor1;
#pragma unroll
            for (int nf = 0; nf < 8; nf++) {
                oacc[nf][0] *= cor0; oacc[nf][1] *= cor0;
                oacc[nf][2] *= cor1; oacc[nf][3] *= cor1;
            }
            for (int nf = 0; nf < nblkS; nf++) {
                sc[nf][0] = __expf(sc[nf][0] - m0);
                sc[nf][1] = __expf(sc[nf][1] - m0);
                sc[nf][2] = __expf(sc[nf][2] - m1);
                sc[nf][3] = __expf(sc[nf][3] - m1);
                l0 += sc[nf][0] + sc[nf][1];
                l1 += sc[nf][2] + sc[nf][3];
            }

            // O += P V : A-frags from own C-layout values (no shuffles), V pre-transposed
            const __half* vsh = sm + (4 + buf) * HTSZ;
            const __half* vsl = sm + (6 + buf) * HTSZ;
            int nkb = nblkS >> 1;
            for (int kb = 0; kb < nkb; kb++) {
                __half h0, e0, h1, e1, h2, e2, h3, e3;
                unsigned ah[4], al[4];
                split_h(sc[2*kb][0], h0, e0);  split_h(sc[2*kb][1], h1, e1);
                ah[0] = pack2(h0, h1); al[0] = pack2(e0, e1);
                split_h(sc[2*kb][2], h2, e2);  split_h(sc[2*kb][3], h3, e3);
                ah[1] = pack2(h2, h3); al[1] = pack2(e2, e3);
                split_h(sc[2*kb+1][0], h0, e0); split_h(sc[2*kb+1][1], h1, e1);
                ah[2] = pack2(h0, h1); al[2] = pack2(e0, e1);
                split_h(sc[2*kb+1][2], h2, e2); split_h(sc[2*kb+1][3], h3, e3);
                ah[3] = pack2(h2, h3); al[3] = pack2(e2, e3);
#pragma unroll
                for (int nf2 = 0; nf2 < 8; nf2++) {
                    int koff = kb * 16 + 2 * c;
                    unsigned bh[2], bl[2];
                    bh[0] = *(const unsigned*)&vsh[(nf2 * 8 + g) * 72 + koff    ];
                    bh[1] = *(const unsigned*)&vsh[(nf2 * 8 + g) * 72 + koff + 8];
                    bl[0] = *(const unsigned*)&vsl[(nf2 * 8 + g) * 72 + koff    ];
                    bl[1] = *(const unsigned*)&vsl[(nf2 * 8 + g) * 72 + koff + 8];
                    mma3h(oacc[nf2], ah, al, bh, bl);
                }
            }
        }
        __syncthreads();
    }

    // finalize
    l0 += __shfl_xor_sync(0xffffffffu, l0, 1);
    l0 += __shfl_xor_sync(0xffffffffu, l0, 2);
    l1 += __shfl_xor_sync(0xffffffffu, l1, 1);
    l1 += __shfl_xor_sync(0xffffffffu, l1, 2);
    float inv0 = 1.0f / l0, inv1 = 1.0f / l1;

    size_t o0 = (size_t)(b * SEQ + qr0) * DMODEL + h * HDIM;
    size_t o1 = (size_t)(b * SEQ + qr1) * DMODEL + h * HDIM;
#pragma unroll
    for (int nf = 0; nf < 8; nf++) {
        int col = nf * 8 + 2 * c;
        split_h(oacc[nf][0] * inv0, oh[o0 + col],     ol[o0 + col]);
        split_h(oacc[nf][1] * inv0, oh[o0 + col + 1], ol[o0 + col + 1]);
        split_h(oacc[nf][2] * inv1, oh[o1 + col],     ol[o1 + col]);
        split_h(oacc[nf][3] * inv1, oh[o1 + col + 1], ol[o1 + col + 1]);
    }
}

// ---------------- launch ----------------
extern "C" void kernel_launch(void* const* d_in, const int* in_sizes, int n_in,
                              void* d_out, int out_size) {
    const float* x  = (const float*)d_in[0];
    const float* Wq = (const float*)d_in[1];
    const float* Wk = (const float*)d_in[2];
    const float* Wv = (const float*)d_in[3];
    const float* Wo = (const float*)d_in[4];
    float* out = (float*)d_out;

    cudaFuncSetAttribute(gemm_f16_kernel, cudaFuncAttributeMaxDynamicSharedMemorySize, GEMM_SMEM);
    cudaFuncSetAttribute(attn_f16_kernel, cudaFuncAttributeMaxDynamicSharedMemorySize, ATTN_SMEM);

    __half *xh, *xl, *wth, *wtl, *qh, *ql, *kh, *kl, *vth, *vtl, *ath, *atl;
    float *qraw, *kraw, *vraw, *ct, *st;
    cudaGetSymbolAddress((void**)&xh,   g_xh);
    cudaGetSymbolAddress((void**)&xl,   g_xl);
    cudaGetSymbolAddress((void**)&wth,  g_wth);
    cudaGetSymbolAddress((void**)&wtl,  g_wtl);
    cudaGetSymbolAddress((void**)&qraw, g_qraw);
    cudaGetSymbolAddress((void**)&kraw, g_kraw);
    cudaGetSymbolAddress((void**)&vraw, g_vraw);
    cudaGetSymbolAddress((void**)&qh,   g_qh);
    cudaGetSymbolAddress((void**)&ql,   g_ql);
    cudaGetSymbolAddress((void**)&kh,   g_kh);
    cudaGetSymbolAddress((void**)&kl,   g_kl);
    cudaGetSymbolAddress((void**)&vth,  g_vth);
    cudaGetSymbolAddress((void**)&vtl,  g_vtl);
    cudaGetSymbolAddress((void**)&ath,  g_ath);
    cudaGetSymbolAddress((void**)&atl,  g_atl);
    cudaGetSymbolAddress((void**)&ct,   g_cos);
    cudaGetSymbolAddress((void**)&st,   g_sin);

    {
        int n = SEQ * (HDIM/2);
        rope_table_kernel<<<(n + 255) / 256, 256>>>(ct, st);
    }

    split_x_kernel<<<(NELEM + 255) / 256, 256>>>(x, xh, xl, NELEM);
    wtrans_kernel<<<dim3(DMODEL/32, DMODEL/32, 4), dim3(32, 32)>>>(Wq, Wk, Wv, Wo, wth, wtl);

    // merged QKV projection (z=0,1,2 -> qraw, kraw, vraw)
    dim3 qkv_grid(DMODEL / 128, MROWS / 128, 3);
    gemm_f16_kernel<<<qkv_grid, 256, GEMM_SMEM>>>(xh, xl,
                                    wth + 0 * WELEM, wtl + 0 * WELEM,
                                    wth + 1 * WELEM, wtl + 1 * WELEM,
                                    wth + 2 * WELEM, wtl + 2 * WELEM,
                                    qraw, kraw, vraw);

    {
        int n = MROWS * NHEADS * 32;
        rope_split_kernel<<<(n + 255) / 256, 256>>>(qraw, kraw, ct, st, qh, ql, kh, kl);
    }
    vtrans_kernel<<<dim3(SEQ/32, DMODEL/32, BATCH), dim3(32, 32)>>>(vraw, vth, vtl);

    attn_f16_kernel<<<dim3(SEQ / 128, NHEADS, BATCH), 256, ATTN_SMEM>>>(
        qh, ql, kh, kl, vth, vtl, ath, atl);

    // output projection
    dim3 o_grid(DMODEL / 128, MROWS / 128, 1);
    gemm_f16_kernel<<<o_grid, 256, GEMM_SMEM>>>(ath, atl,
                                  wth + 3 * WELEM, wtl + 3 * WELEM,
                                  wth + 3 * WELEM, wtl + 3 * WELEM,
                                  wth + 3 * WELEM, wtl + 3 * WELEM,
                                  out, out, out);
}

// round 7
// speedup vs baseline: 4.1025x; 1.0378x over previous
#include <cuda_runtime.h>
#include <cuda_fp16.h>
#include <math.h>

#define BATCH 2
#define SEQ   2048
#define DMODEL 768
#define NHEADS 12
#define HDIM  64
#define MROWS (BATCH*SEQ)   // 4096
#define NELEM (MROWS*DMODEL)
#define WELEM (DMODEL*DMODEL)

// ---------------- scratch (device globals; allocation-free) ----------------
__device__ __half g_xh[NELEM],  g_xl[NELEM];
__device__ __half g_wth[4][WELEM], g_wtl[4][WELEM];   // transposed [n][k]
__device__ float  g_qraw[NELEM], g_kraw[NELEM], g_vraw[NELEM];
__device__ __half g_qh[NELEM], g_ql[NELEM];
__device__ __half g_kh[NELEM], g_kl[NELEM];
__device__ __half g_vth[NELEM], g_vtl[NELEM];          // [b][dglobal][t]
__device__ __half g_ath[NELEM], g_atl[NELEM];
__device__ float  g_cos[SEQ * (HDIM/2)];
__device__ float  g_sin[SEQ * (HDIM/2)];

// ---------------- fp16-split helpers ----------------
__device__ __forceinline__ void split_h(float x, __half& h, __half& l) {
    h = __float2half_rn(x);
    l = __float2half_rn(x - __half2float(h));
}
__device__ __forceinline__ unsigned pack2(__half a, __half b) {
    __half2 t = __halves2half2(a, b);
    return *(unsigned*)&t;
}
__device__ __forceinline__ void mma_f16(float* d, const unsigned* a, const unsigned* b, const float* c) {
    asm volatile(
        "mma.sync.aligned.m16n8k16.row.col.f32.f16.f16.f32 "
        "{%0,%1,%2,%3}, {%4,%5,%6,%7}, {%8,%9}, {%10,%11,%12,%13};\n"
        : "=f"(d[0]), "=f"(d[1]), "=f"(d[2]), "=f"(d[3])
        : "r"(a[0]), "r"(a[1]), "r"(a[2]), "r"(a[3]),
          "r"(b[0]), "r"(b[1]),
          "f"(c[0]), "f"(c[1]), "f"(c[2]), "f"(c[3]));
}
__device__ __forceinline__ void mma3h(float* d, const unsigned* ah, const unsigned* al,
                                      const unsigned* bh, const unsigned* bl) {
    mma_f16(d, al, bh, d);
    mma_f16(d, ah, bl, d);
    mma_f16(d, ah, bh, d);
}
__device__ __forceinline__ void ldsm_x4(unsigned* r, unsigned addr) {
    asm volatile("ldmatrix.sync.aligned.m8n8.x4.shared.b16 {%0,%1,%2,%3}, [%4];"
        : "=r"(r[0]), "=r"(r[1]), "=r"(r[2]), "=r"(r[3]) : "r"(addr));
}

__device__ __forceinline__ void cp_async16(void* smem, const void* gmem) {
    unsigned s = (unsigned)__cvta_generic_to_shared(smem);
    asm volatile("cp.async.cg.shared.global [%0], [%1], 16;\n" :: "r"(s), "l"(gmem));
}
__device__ __forceinline__ void cp_commit() { asm volatile("cp.async.commit_group;\n"); }
template<int N> __device__ __forceinline__ void cp_wait() {
    asm volatile("cp.async.wait_group %0;\n" :: "n"(N));
}

// ---------------- prepass: x split ----------------
__global__ void split_x_kernel(const float* __restrict__ src, __half* __restrict__ hi,
                               __half* __restrict__ lo, int n) {
    int i = blockIdx.x * blockDim.x + threadIdx.x;
    if (i >= n) return;
    split_h(src[i], hi[i], lo[i]);
}

// ---------------- prepass: weight transpose + split -> Wt[n][k] ----------------
__global__ void wtrans_kernel(const float* __restrict__ w0, const float* __restrict__ w1,
                              const float* __restrict__ w2, const float* __restrict__ w3,
                              __half* __restrict__ hi, __half* __restrict__ lo) {
    __shared__ float t[32][33];
    int w = blockIdx.z;
    const float* W = (w == 0) ? w0 : (w == 1) ? w1 : (w == 2) ? w2 : w3;
    int k0 = blockIdx.x * 32, n0 = blockIdx.y * 32;
    int tx = threadIdx.x, ty = threadIdx.y;
    t[ty][tx] = W[(size_t)(k0 + ty) * DMODEL + n0 + tx];
    __syncthreads();
    float v = t[tx][ty];
    size_t o = (size_t)w * WELEM + (size_t)(n0 + ty) * DMODEL + k0 + tx;
    split_h(v, hi[o], lo[o]);
}

// ---------------- prepass: V transpose + split -> vt[b][dglobal][t] ----------------
__global__ void vtrans_kernel(const float* __restrict__ vraw,
                              __half* __restrict__ hi, __half* __restrict__ lo) {
    __shared__ float t[32][33];
    int b = blockIdx.z;
    int t0 = blockIdx.x * 32, d0 = blockIdx.y * 32;
    int tx = threadIdx.x, ty = threadIdx.y;
    t[ty][tx] = vraw[(size_t)(b * SEQ + t0 + ty) * DMODEL + d0 + tx];
    __syncthreads();
    float v = t[tx][ty];
    size_t o = ((size_t)b * DMODEL + d0 + ty) * SEQ + t0 + tx;
    split_h(v, hi[o], lo[o]);
}

// ---------------- RoPE table ----------------
__global__ void rope_table_kernel(float* ct, float* st) {
    int idx = blockIdx.x * blockDim.x + threadIdx.x;
    if (idx >= SEQ * (HDIM/2)) return;
    int t = idx >> 5;
    int i = idx & 31;
    float inv_freq = powf(10000.0f, -(float)(2 * i) / (float)HDIM);
    float ang = (float)t * inv_freq;
    ct[idx] = cosf(ang);
    st[idx] = sinf(ang);
}

// ---------------- fused RoPE + fp16 split (q scaled by 0.125) ----------------
__global__ void rope_split_kernel(const float* __restrict__ q, const float* __restrict__ k,
                                  const float* __restrict__ ct, const float* __restrict__ st,
                                  __half* qh, __half* ql, __half* kh, __half* kl) {
    int idx = blockIdx.x * blockDim.x + threadIdx.x;
    if (idx >= MROWS * NHEADS * 32) return;
    int i   = idx & 31;
    int h   = (idx >> 5) % NHEADS;
    int row = idx / (32 * NHEADS);
    int t   = row % SEQ;
    float c = ct[t * 32 + i];
    float s = st[t * 32 + i];
    size_t base = (size_t)row * DMODEL + h * HDIM;
    float x1 = q[base + i], x2 = q[base + 32 + i];
    split_h((x1 * c - x2 * s) * 0.125f, qh[base + i],      ql[base + i]);
    split_h((x1 * s + x2 * c) * 0.125f, qh[base + 32 + i], ql[base + 32 + i]);
    x1 = k[base + i]; x2 = k[base + 32 + i];
    split_h(x1 * c - x2 * s, kh[base + i],      kl[base + i]);
    split_h(x1 * s + x2 * c, kh[base + 32 + i], kl[base + 32 + i]);
}

// ---------------- 3xFP16 GEMM with ldmatrix fragment loads ----------------
// C[4096,768] = A[4096,768] @ Bt. 128x128 tile, BK=32, 256 threads, warp 32x64.
#define GEMM_SMEM 81920

__global__ __launch_bounds__(256, 2)
void gemm_f16_kernel(const __half* __restrict__ Ah, const __half* __restrict__ Al,
                     const __half* __restrict__ B0h, const __half* __restrict__ B0l,
                     const __half* __restrict__ B1h, const __half* __restrict__ B1l,
                     const __half* __restrict__ B2h, const __half* __restrict__ B2l,
                     float* __restrict__ C0, float* __restrict__ C1, float* __restrict__ C2) {
    const int K = DMODEL, N = DMODEL;
    extern __shared__ __half smh[];
    // halves layout: As_h [2][128][40] @0 | As_l @10240 | Bs_h @20480 | Bs_l @30720

    int z = blockIdx.z;
    const __half* Bh = (z == 0) ? B0h : (z == 1) ? B1h : B2h;
    const __half* Bl = (z == 0) ? B0l : (z == 1) ? B1l : B2l;
    float* C = (z == 0) ? C0 : (z == 1) ? C1 : C2;

    int tid  = threadIdx.x;
    int wid  = tid >> 5, lane = tid & 31;
    int g = lane >> 2, c = lane & 3;
    int wm = (wid & 3) * 32;
    int wn = (wid >> 2) * 64;
    int bm = blockIdx.y * 128, bn = blockIdx.x * 128;

    int lrow = tid >> 1, lseg = (tid & 1) * 16;

    // ldmatrix per-thread byte offsets (within a buffer)
    unsigned smem_u = (unsigned)__cvta_generic_to_shared(smh);
    unsigned a_frag = smem_u + ((wm + (lane & 15)) * 40 + ((lane & 16) ? 8 : 0)) * 2;
    unsigned b_frag = smem_u + 40960 +
                      ((wn + (lane & 7) + ((lane & 16) ? 8 : 0)) * 40 + ((lane & 8) ? 8 : 0)) * 2;

    float acc[2][8][4];
#pragma unroll
    for (int mf = 0; mf < 2; mf++)
#pragma unroll
        for (int nf = 0; nf < 8; nf++)
#pragma unroll
            for (int j = 0; j < 4; j++) acc[mf][nf][j] = 0.0f;

    auto load_chunk = [&](int buf, int k0) {
        size_t ga = (size_t)(bm + lrow) * K + k0 + lseg;
        __half* da_h = smh + buf * 5120 + lrow * 40 + lseg;
        __half* da_l = da_h + 10240;
        cp_async16(da_h,     Ah + ga);
        cp_async16(da_h + 8, Ah + ga + 8);
        cp_async16(da_l,     Al + ga);
        cp_async16(da_l + 8, Al + ga + 8);
        size_t gb = (size_t)(bn + lrow) * K + k0 + lseg;
        __half* db_h = smh + 20480 + buf * 5120 + lrow * 40 + lseg;
        __half* db_l = db_h + 10240;
        cp_async16(db_h,     Bh + gb);
        cp_async16(db_h + 8, Bh + gb + 8);
        cp_async16(db_l,     Bl + gb);
        cp_async16(db_l + 8, Bl + gb + 8);
    };

    const int NCH = K / 32;  // 24
    load_chunk(0, 0); cp_commit();

    for (int ch = 0; ch < NCH; ch++) {
        int buf = ch & 1;
        if (ch + 1 < NCH) { load_chunk(buf ^ 1, (ch + 1) * 32); cp_commit(); cp_wait<1>(); }
        else              { cp_wait<0>(); }
        __syncthreads();

        unsigned abase = a_frag + buf * 10240;
        unsigned bbase = b_frag + buf * 10240;
#pragma unroll
        for (int ks = 0; ks < 2; ks++) {
            int kb = ks * 32;
            unsigned afh[2][4], afl[2][4], bfh[8][2], bfl[8][2];
            ldsm_x4(afh[0], abase + kb);
            ldsm_x4(afh[1], abase + 1280 + kb);
            ldsm_x4(afl[0], abase + 20480 + kb);
            ldsm_x4(afl[1], abase + 20480 + 1280 + kb);
#pragma unroll
            for (int p = 0; p < 4; p++) {
                unsigned r[4];
                ldsm_x4(r, bbase + p * 1280 + kb);
                bfh[2*p][0] = r[0]; bfh[2*p][1] = r[1]; bfh[2*p+1][0] = r[2]; bfh[2*p+1][1] = r[3];
                ldsm_x4(r, bbase + 20480 + p * 1280 + kb);
                bfl[2*p][0] = r[0]; bfl[2*p][1] = r[1]; bfl[2*p+1][0] = r[2]; bfl[2*p+1][1] = r[3];
            }
#pragma unroll
            for (int mf = 0; mf < 2; mf++)
#pragma unroll
                for (int nf = 0; nf < 8; nf++)
                    mma3h(acc[mf][nf], afh[mf], afl[mf], bfh[nf], bfl[nf]);
        }
        __syncthreads();
    }

#pragma unroll
    for (int mf = 0; mf < 2; mf++) {
        int row0 = bm + wm + mf * 16 + g;
#pragma unroll
        for (int nf = 0; nf < 8; nf++) {
            int col = bn + wn + nf * 8 + 2 * c;
            *(float2*)(C + (size_t)row0 * N + col)       = make_float2(acc[mf][nf][0], acc[mf][nf][1]);
            *(float2*)(C + (size_t)(row0 + 8) * N + col) = make_float2(acc[mf][nf][2], acc[mf][nf][3]);
        }
    }
}

// ---------------- 3xFP16 causal flash attention with ldmatrix ----------------
#define HTSZ (64 * 72)                 // halves per tile
#define HTB  (HTSZ * 2)                // bytes per tile = 9216
#define ATTN_SMEM (8 * HTB)            // 73728 B

__global__ __launch_bounds__(256, 2)
void attn_f16_kernel(const __half* __restrict__ qh, const __half* __restrict__ ql,
                     const __half* __restrict__ kh, const __half* __restrict__ kl,
                     const __half* __restrict__ vth, const __half* __restrict__ vtl,
                     __half* __restrict__ oh, __half* __restrict__ ol) {
    extern __shared__ __half sm[];
    // tiles (bytes): KH[buf]@buf*HTB | KL@(2+buf)*HTB | VH@(4+buf)*HTB | VL@(6+buf)*HTB

    int qt = gridDim.x - 1 - blockIdx.x;   // heaviest blocks first
    int h = blockIdx.y, b = blockIdx.z;
    int tid = threadIdx.x;
    int warp = tid >> 5, lane = tid & 31;
    int g = lane >> 2, c = lane & 3;
    int qbase_w = qt * 128 + warp * 16;

    unsigned smem_u = (unsigned)__cvta_generic_to_shared(sm);
    unsigned kv_frag = smem_u + ((lane & 7) + ((lane & 16) ? 8 : 0)) * 144 + ((lane & 8) ? 16 : 0);

    // Q fragments
    unsigned qfh[4][4], qfl[4][4];
    {
        size_t b0 = (size_t)(b * SEQ + qbase_w + g)     * DMODEL + h * HDIM;
        size_t b1 = (size_t)(b * SEQ + qbase_w + g + 8) * DMODEL + h * HDIM;
#pragma unroll
        for (int ks = 0; ks < 4; ks++) {
            int k0 = ks * 16 + 2 * c;
            qfh[ks][0] = *(const unsigned*)&qh[b0 + k0];
            qfh[ks][1] = *(const unsigned*)&qh[b1 + k0];
            qfh[ks][2] = *(const unsigned*)&qh[b0 + k0 + 8];
            qfh[ks][3] = *(const unsigned*)&qh[b1 + k0 + 8];
            qfl[ks][0] = *(const unsigned*)&ql[b0 + k0];
            qfl[ks][1] = *(const unsigned*)&ql[b1 + k0];
            qfl[ks][2] = *(const unsigned*)&ql[b0 + k0 + 8];
            qfl[ks][3] = *(const unsigned*)&ql[b1 + k0 + 8];
        }
    }

    float oacc[8][4];
#pragma unroll
    for (int nf = 0; nf < 8; nf++)
#pragma unroll
        for (int j = 0; j < 4; j++) oacc[nf][j] = 0.0f;
    float m0 = -1e30f, m1 = -1e30f, l0 = 0.0f, l1 = 0.0f;
    int qr0 = qbase_w + g;
    int qr1 = qr0 + 8;

    auto load_kv = [&](int buf, int kt) {
        size_t kb_ = (size_t)(b * SEQ + kt * 64) * DMODEL + h * HDIM;
        size_t vb_ = ((size_t)b * DMODEL + h * HDIM) * SEQ + kt * 64;
        __half* dkh = sm + buf * HTSZ;
        __half* dkl = sm + (2 + buf) * HTSZ;
        __half* dvh = sm + (4 + buf) * HTSZ;
        __half* dvl = sm + (6 + buf) * HTSZ;
#pragma unroll
        for (int i = tid; i < 64 * 8; i += 256) {
            int row = i >> 3, seg = (i & 7) * 8;
            int so = row * 72 + seg;
            cp_async16(dkh + so, kh  + kb_ + (size_t)row * DMODEL + seg);
            cp_async16(dkl + so, kl  + kb_ + (size_t)row * DMODEL + seg);
            cp_async16(dvh + so, vth + vb_ + (size_t)row * SEQ    + seg);
            cp_async16(dvl + so, vtl + vb_ + (size_t)row * SEQ    + seg);
        }
    };

    const int kt_max = 2 * qt + 1;
    load_kv(0, 0); cp_commit();

    for (int kt = 0; kt <= kt_max; kt++) {
        int buf = kt & 1;
        if (kt < kt_max) { load_kv(buf ^ 1, kt + 1); cp_commit(); cp_wait<1>(); }
        else             { cp_wait<0>(); }
        __syncthreads();

        int rel = qbase_w + 15 - kt * 64;
        int nblk = (rel < 0) ? 0 : min(8, (rel >> 3) + 1);
        int nblkS = (nblk + 1) & ~1;
        bool need_mask = (kt * 64 + 63 > qbase_w);

        if (nblkS > 0) {
            unsigned kh_b = kv_frag + buf * HTB;
            unsigned kl_b = kv_frag + (2 + buf) * HTB;

            // S = Q K^T
            float sc[8][4];
            int npair = nblkS >> 1;
            for (int p = 0; p < npair; p++) {
#pragma unroll
                for (int j = 0; j < 4; j++) { sc[2*p][j] = 0.0f; sc[2*p+1][j] = 0.0f; }
#pragma unroll
                for (int ks = 0; ks < 4; ks++) {
                    unsigned bh[4], bl[4];
                    ldsm_x4(bh, kh_b + p * 2304 + ks * 32);
                    ldsm_x4(bl, kl_b + p * 2304 + ks * 32);
                    mma3h(sc[2*p],   qfh[ks], qfl[ks], bh,     bl);
                    mma3h(sc[2*p+1], qfh[ks], qfl[ks], bh + 2, bl + 2);
                }
            }

            if (need_mask) {
                for (int nf = 0; nf < nblkS; nf++) {
#pragma unroll
                    for (int j = 0; j < 4; j++) {
                        int key = kt * 64 + nf * 8 + 2 * c + (j & 1);
                        int qr  = (j < 2) ? qr0 : qr1;
                        if (key > qr) sc[nf][j] = -1e30f;
                    }
                }
            }

            // online softmax
            float mx0 = -1e30f, mx1 = -1e30f;
            for (int nf = 0; nf < nblkS; nf++) {
                mx0 = fmaxf(mx0, fmaxf(sc[nf][0], sc[nf][1]));
                mx1 = fmaxf(mx1, fmaxf(sc[nf][2], sc[nf][3]));
            }
            mx0 = fmaxf(mx0, __shfl_xor_sync(0xffffffffu, mx0, 1));
            mx0 = fmaxf(mx0, __shfl_xor_sync(0xffffffffu, mx0, 2));
            mx1 = fmaxf(mx1, __shfl_xor_sync(0xffffffffu, mx1, 1));
            mx1 = fmaxf(mx1, __shfl_xor_sync(0xffffffffu, mx1, 2));
            float nm0 = fmaxf(m0, mx0), nm1 = fmaxf(m1, mx1);
            float cor0 = __expf(m0 - nm0), cor1 = __expf(m1 - nm1);
            m0 = nm0; m1 = nm1;
            l0 *= cor0; l1 *= cor1;
#pragma unroll
            for (int nf = 0; nf < 8; nf++) {
                oacc[nf][0] *= cor0; oacc[nf][1] *= cor0;
                oacc[nf][2] *= cor1; oacc[nf][3] *= cor1;
            }
            for (int nf = 0; nf < nblkS; nf++) {
                sc[nf][0] = __expf(sc[nf][0] - m0);
                sc[nf][1] = __expf(sc[nf][1] - m0);
                sc[nf][2] = __expf(sc[nf][2] - m1);
                sc[nf][3] = __expf(sc[nf][3] - m1);
                l0 += sc[nf][0] + sc[nf][1];
                l1 += sc[nf][2] + sc[nf][3];
            }

            // O += P V (A-frags from own C-layout values; V pre-transposed)
            unsigned vh_b = kv_frag + (4 + buf) * HTB;
            unsigned vl_b = kv_frag + (6 + buf) * HTB;
            int nkb = nblkS >> 1;
            for (int kb = 0; kb < nkb; kb++) {
                __half h0, e0, h1, e1, h2, e2, h3, e3;
                unsigned ah[4], al[4];
                split_h(sc[2*kb][0], h0, e0);  split_h(sc[2*kb][1], h1, e1);
                ah[0] = pack2(h0, h1); al[0] = pack2(e0, e1);
                split_h(sc[2*kb][2], h2, e2);  split_h(sc[2*kb][3], h3, e3);
                ah[1] = pack2(h2, h3); al[1] = pack2(e2, e3);
                split_h(sc[2*kb+1][0], h0, e0); split_h(sc[2*kb+1][1], h1, e1);
                ah[2] = pack2(h0, h1); al[2] = pack2(e0, e1);
                split_h(sc[2*kb+1][2], h2, e2); split_h(sc[2*kb+1][3], h3, e3);
                ah[3] = pack2(h2, h3); al[3] = pack2(e2, e3);
#pragma unroll
                for (int p = 0; p < 4; p++) {
                    unsigned bh[4], bl[4];
                    ldsm_x4(bh, vh_b + p * 2304 + kb * 32);
                    ldsm_x4(bl, vl_b + p * 2304 + kb * 32);
                    mma3h(oacc[2*p],   ah, al, bh,     bl);
                    mma3h(oacc[2*p+1], ah, al, bh + 2, bl + 2);
                }
            }
        }
        __syncthreads();
    }

    // finalize
    l0 += __shfl_xor_sync(0xffffffffu, l0, 1);
    l0 += __shfl_xor_sync(0xffffffffu, l0, 2);
    l1 += __shfl_xor_sync(0xffffffffu, l1, 1);
    l1 += __shfl_xor_sync(0xffffffffu, l1, 2);
    float inv0 = 1.0f / l0, inv1 = 1.0f / l1;

    size_t o0 = (size_t)(b * SEQ + qr0) * DMODEL + h * HDIM;
    size_t o1 = (size_t)(b * SEQ + qr1) * DMODEL + h * HDIM;
#pragma unroll
    for (int nf = 0; nf < 8; nf++) {
        int col = nf * 8 + 2 * c;
        split_h(oacc[nf][0] * inv0, oh[o0 + col],     ol[o0 + col]);
        split_h(oacc[nf][1] * inv0, oh[o0 + col + 1], ol[o0 + col + 1]);
        split_h(oacc[nf][2] * inv1, oh[o1 + col],     ol[o1 + col]);
        split_h(oacc[nf][3] * inv1, oh[o1 + col + 1], ol[o1 + col + 1]);
    }
}

// ---------------- launch ----------------
extern "C" void kernel_launch(void* const* d_in, const int* in_sizes, int n_in,
                              void* d_out, int out_size) {
    const float* x  = (const float*)d_in[0];
    const float* Wq = (const float*)d_in[1];
    const float* Wk = (const float*)d_in[2];
    const float* Wv = (const float*)d_in[3];
    const float* Wo = (const float*)d_in[4];
    float* out = (float*)d_out;

    cudaFuncSetAttribute(gemm_f16_kernel, cudaFuncAttributeMaxDynamicSharedMemorySize, GEMM_SMEM);
    cudaFuncSetAttribute(attn_f16_kernel, cudaFuncAttributeMaxDynamicSharedMemorySize, ATTN_SMEM);

    __half *xh, *xl, *wth, *wtl, *qh, *ql, *kh, *kl, *vth, *vtl, *ath, *atl;
    float *qraw, *kraw, *vraw, *ct, *st;
    cudaGetSymbolAddress((void**)&xh,   g_xh);
    cudaGetSymbolAddress((void**)&xl,   g_xl);
    cudaGetSymbolAddress((void**)&wth,  g_wth);
    cudaGetSymbolAddress((void**)&wtl,  g_wtl);
    cudaGetSymbolAddress((void**)&qraw, g_qraw);
    cudaGetSymbolAddress((void**)&kraw, g_kraw);
    cudaGetSymbolAddress((void**)&vraw, g_vraw);
    cudaGetSymbolAddress((void**)&qh,   g_qh);
    cudaGetSymbolAddress((void**)&ql,   g_ql);
    cudaGetSymbolAddress((void**)&kh,   g_kh);
    cudaGetSymbolAddress((void**)&kl,   g_kl);
    cudaGetSymbolAddress((void**)&vth,  g_vth);
    cudaGetSymbolAddress((void**)&vtl,  g_vtl);
    cudaGetSymbolAddress((void**)&ath,  g_ath);
    cudaGetSymbolAddress((void**)&atl,  g_atl);
    cudaGetSymbolAddress((void**)&ct,   g_cos);
    cudaGetSymbolAddress((void**)&st,   g_sin);

    {
        int n = SEQ * (HDIM/2);
        rope_table_kernel<<<(n + 255) / 256, 256>>>(ct, st);
    }

    split_x_kernel<<<(NELEM + 255) / 256, 256>>>(x, xh, xl, NELEM);
    wtrans_kernel<<<dim3(DMODEL/32, DMODEL/32, 4), dim3(32, 32)>>>(Wq, Wk, Wv, Wo, wth, wtl);

    dim3 qkv_grid(DMODEL / 128, MROWS / 128, 3);
    gemm_f16_kernel<<<qkv_grid, 256, GEMM_SMEM>>>(xh, xl,
                                    wth + 0 * WELEM, wtl + 0 * WELEM,
                                    wth + 1 * WELEM, wtl + 1 * WELEM,
                                    wth + 2 * WELEM, wtl + 2 * WELEM,
                                    qraw, kraw, vraw);

    {
        int n = MROWS * NHEADS * 32;
        rope_split_kernel<<<(n + 255) / 256, 256>>>(qraw, kraw, ct, st, qh, ql, kh, kl);
    }
    vtrans_kernel<<<dim3(SEQ/32, DMODEL/32, BATCH), dim3(32, 32)>>>(vraw, vth, vtl);

    attn_f16_kernel<<<dim3(SEQ / 128, NHEADS, BATCH), 256, ATTN_SMEM>>>(
        qh, ql, kh, kl, vth, vtl, ath, atl);

    dim3 o_grid(DMODEL / 128, MROWS / 128, 1);
    gemm_f16_kernel<<<o_grid, 256, GEMM_SMEM>>>(ath, atl,
                                  wth + 3 * WELEM, wtl + 3 * WELEM,
                                  wth + 3 * WELEM, wtl + 3 * WELEM,
                                  wth + 3 * WELEM, wtl + 3 * WELEM,
                                  out, out, out);
}